// round 1
// baseline (speedup 1.0000x reference)
#include <cuda_runtime.h>
#include <math.h>

#define B_  20
#define S_  500
#define D_  300
#define H_  600
#define QK_ 128

// ---------------- scratch (device globals; no allocation) ----------------
__device__ float g_nx[B_*S_*D_];
__device__ float g_qkbuf[B_*S_*QK_];
__device__ float g_q[B_*S_*QK_];
__device__ float g_k[B_*S_*QK_];
__device__ float g_v[B_*S_*H_];
__device__ float g_gate[B_*S_*H_];
__device__ float g_attn[(size_t)B_*S_*S_];
__device__ float g_o[B_*S_*H_];
__device__ float g_bias[1024];                 // 999 used: delta in [-499,499]
__device__ int   g_hist[B_*129];
__device__ unsigned g_gmax[B_];
__device__ int   g_trim[B_];
__device__ unsigned char g_counts[B_*100*120];
__device__ int   g_cmax[B_];
__device__ int   g_hist2[B_*17];
__device__ int   g_t2[B_];

// ---------------- accurate fp32 exp (robust to --use_fast_math) ----------------
__device__ __forceinline__ float my_expf(float x){
    x = fminf(fmaxf(x, -87.0f), 87.0f);
    float t = fmaf(x, 1.4426950408889634f, 12582912.0f);
    float n = t - 12582912.0f;                     // round(x/ln2)
    float r = fmaf(n, -0.693359375f, x);           // x - n*ln2_hi
    r = fmaf(n, 2.1219444005469058e-4f, r);        // - n*ln2_lo
    float p = 1.9841269841e-4f;                    // 1/5040
    p = fmaf(p, r, 1.3888888889e-3f);
    p = fmaf(p, r, 8.3333333333e-3f);
    p = fmaf(p, r, 4.1666666667e-2f);
    p = fmaf(p, r, 1.6666666667e-1f);
    p = fmaf(p, r, 0.5f);
    p = fmaf(p, r, 1.0f);
    p = fmaf(p, r, 1.0f);
    int e = (int)n;
    return p * __int_as_float((e + 127) << 23);
}
__device__ __forceinline__ float silu_f(float v){
    return v / (1.0f + my_expf(-v));
}

// ---------------- init: zero stats + build t5 bias table ----------------
__global__ void init_kernel(const float* __restrict__ rel_emb){
    int i = blockIdx.x * blockDim.x + threadIdx.x;
    if (i < B_*129) g_hist[i] = 0;
    if (i < B_*17)  g_hist2[i] = 0;
    if (i < B_)     { g_gmax[i] = 0u; g_cmax[i] = 0; }
    if (i < 999){
        int n = i - (S_-1);
        int ret = (n < 0) ? 16 : 0;
        int na = n < 0 ? -n : n;
        int bucket;
        if (na < 8) bucket = ret + na;
        else {
            // replicate jax fp32 rounding: fp32 log, correctly-rounded fp32 div, *8
            float lnum = (float)log((double)na / 8.0);
            float lden = (float)log(16.0);
            float q = (float)((double)lnum / (double)lden);
            int vil = 8 + (int)(q * 8.0f);
            if (vil > 15) vil = 15;
            bucket = ret + vil;
        }
        g_bias[i] = rel_emb[bucket] * sqrtf(128.0f);
    }
}

// ---------------- LayerNorm + token-shift of first half ----------------
__global__ __launch_bounds__(128) void ln_kernel(const float* __restrict__ x,
                                                 const float* __restrict__ g,
                                                 const float* __restrict__ b){
    int bs = blockIdx.x;
    int batch = bs / S_, s = bs % S_;
    const float* xr = x + (size_t)bs * D_;
    __shared__ float red[128];
    int tid = threadIdx.x;
    float sum = 0.f;
    for (int i = tid; i < D_; i += 128) sum += xr[i];
    red[tid] = sum; __syncthreads();
    for (int off = 64; off > 0; off >>= 1){ if (tid < off) red[tid] += red[tid+off]; __syncthreads(); }
    float mean = red[0] * (1.0f / D_);
    __syncthreads();
    float vs = 0.f;
    for (int i = tid; i < D_; i += 128){ float d = xr[i]-mean; vs += d*d; }
    red[tid] = vs; __syncthreads();
    for (int off = 64; off > 0; off >>= 1){ if (tid < off) red[tid] += red[tid+off]; __syncthreads(); }
    float var = red[0] * (1.0f / D_);
    float inv = rsqrtf(var + 1e-5f);
    for (int i = tid; i < D_; i += 128){
        float val = (xr[i]-mean)*inv*g[i] + b[i];
        if (i < D_/2){
            if (s+1 < S_) g_nx[((size_t)batch*S_ + s+1)*D_ + i] = val;   // shifted
        } else {
            g_nx[(size_t)bs*D_ + i] = val;
        }
    }
    if (s == 0){ for (int i = tid; i < D_/2; i += 128) g_nx[(size_t)bs*D_ + i] = 0.f; }
}

// ---------------- tiled SGEMM (NN + NT flavors, functor epilogues) ----------------
#define BM 64
#define BN 64
#define BK 16

template<class Epi>
__global__ __launch_bounds__(256) void sgemm_nn(const float* __restrict__ A,
                                                const float* __restrict__ B,
                                                int M, int N, int K, int lda, int ldb,
                                                long sA, long sB, Epi epi){
    int bz = blockIdx.z;
    A += (size_t)bz * sA;  B += (size_t)bz * sB;
    __shared__ float As[BK][BM+1];
    __shared__ float Bs[BK][BN+1];
    int row0 = blockIdx.y * BM, col0 = blockIdx.x * BN;
    int tid = threadIdx.x, tx = tid & 15, ty = tid >> 4;
    float acc[4][4] = {};
    for (int k0 = 0; k0 < K; k0 += BK){
        for (int l = tid; l < BM*BK; l += 256){
            int i = l / BK, kk = l % BK;
            int r = row0 + i, c = k0 + kk;
            As[kk][i] = (r < M && c < K) ? A[(size_t)r*lda + c] : 0.f;
        }
        for (int l = tid; l < BK*BN; l += 256){
            int kk = l / BN, j = l % BN;
            int r = k0 + kk, c = col0 + j;
            Bs[kk][j] = (r < K && c < N) ? B[(size_t)r*ldb + c] : 0.f;
        }
        __syncthreads();
        #pragma unroll
        for (int kk = 0; kk < BK; kk++){
            float a[4], bb[4];
            #pragma unroll
            for (int m = 0; m < 4; m++) a[m]  = As[kk][ty*4+m];
            #pragma unroll
            for (int n = 0; n < 4; n++) bb[n] = Bs[kk][tx*4+n];
            #pragma unroll
            for (int m = 0; m < 4; m++)
                #pragma unroll
                for (int n = 0; n < 4; n++) acc[m][n] = fmaf(a[m], bb[n], acc[m][n]);
        }
        __syncthreads();
    }
    #pragma unroll
    for (int m = 0; m < 4; m++){
        int r = row0 + ty*4 + m;
        if (r >= M) continue;
        #pragma unroll
        for (int n = 0; n < 4; n++){
            int c = col0 + tx*4 + n;
            if (c < N) epi(bz, r, c, acc[m][n]);
        }
    }
}

template<class Epi>
__global__ __launch_bounds__(256) void sgemm_nt(const float* __restrict__ A,
                                                const float* __restrict__ B,   // B is N x K row-major
                                                int M, int N, int K, int lda, int ldb,
                                                long sA, long sB, Epi epi){
    int bz = blockIdx.z;
    A += (size_t)bz * sA;  B += (size_t)bz * sB;
    __shared__ float As[BK][BM+1];
    __shared__ float Bs[BK][BN+1];
    int row0 = blockIdx.y * BM, col0 = blockIdx.x * BN;
    int tid = threadIdx.x, tx = tid & 15, ty = tid >> 4;
    float acc[4][4] = {};
    for (int k0 = 0; k0 < K; k0 += BK){
        for (int l = tid; l < BM*BK; l += 256){
            int i = l / BK, kk = l % BK;
            int r = row0 + i, c = k0 + kk;
            As[kk][i] = (r < M && c < K) ? A[(size_t)r*lda + c] : 0.f;
        }
        for (int l = tid; l < BN*BK; l += 256){
            int j = l / BK, kk = l % BK;
            int r = col0 + j, c = k0 + kk;
            Bs[kk][j] = (r < N && c < K) ? B[(size_t)r*ldb + c] : 0.f;
        }
        __syncthreads();
        #pragma unroll
        for (int kk = 0; kk < BK; kk++){
            float a[4], bb[4];
            #pragma unroll
            for (int m = 0; m < 4; m++) a[m]  = As[kk][ty*4+m];
            #pragma unroll
            for (int n = 0; n < 4; n++) bb[n] = Bs[kk][tx*4+n];
            #pragma unroll
            for (int m = 0; m < 4; m++)
                #pragma unroll
                for (int n = 0; n < 4; n++) acc[m][n] = fmaf(a[m], bb[n], acc[m][n]);
        }
        __syncthreads();
    }
    #pragma unroll
    for (int m = 0; m < 4; m++){
        int r = row0 + ty*4 + m;
        if (r >= M) continue;
        #pragma unroll
        for (int n = 0; n < 4; n++){
            int c = col0 + tx*4 + n;
            if (c < N) epi(bz, r, c, acc[m][n]);
        }
    }
}

// ---------------- epilogues ----------------
struct EpiH {
    const float* bh;
    __device__ void operator()(int, int r, int c, float acc) const {
        float s = silu_f(acc + bh[c]);
        if (c < H_) g_v[(size_t)r*H_ + c] = s;
        else        g_gate[(size_t)r*H_ + (c - H_)] = s;
    }
};
struct EpiQK {
    const float* bqk;
    __device__ void operator()(int, int r, int c, float acc) const {
        g_qkbuf[(size_t)r*QK_ + c] = silu_f(acc + bqk[c]);
    }
};
struct EpiScores {
    const float* mask2;
    __device__ void operator()(int bz, int r, int c, float acc) const {
        float val = acc + g_bias[r - c + (S_-1)];
        float t = fmaxf(val * (1.0f / S_), 0.0f);
        g_attn[((size_t)bz*S_ + r)*S_ + c] = t * t * mask2[r*S_ + c];
    }
};
struct EpiOut {
    __device__ void operator()(int bz, int r, int c, float acc) const {
        int rr = r % 5, cc = c % 5;
        float m = 0.0f;
        if (rr != 4 && cc != 4){
            int cnt = g_counts[bz*12000 + (r/5)*120 + (c/5)];
            m = (cnt >= g_t2[bz]) ? 1.0f : 0.25f;
        }
        size_t idx = ((size_t)bz*S_ + r)*H_ + c;
        g_o[idx] = m * acc * g_gate[idx];
    }
};
struct EpiFinal {
    const float* bout;
    const float* x;
    float* out;
    __device__ void operator()(int, int r, int c, float acc) const {
        out[(size_t)r*D_ + c] = acc + bout[c] + x[(size_t)r*D_ + c];
    }
};

// ---------------- rotary on q/k ----------------
__global__ __launch_bounds__(128) void rotary_kernel(const float* __restrict__ gamma,
                                                     const float* __restrict__ beta){
    int bs = blockIdx.x;
    int s = bs % S_;
    int d = threadIdx.x;
    size_t base = (size_t)bs * QK_;
    float v  = g_qkbuf[base + d];
    float qv = fmaf(v, gamma[d],       beta[d]);
    float kv = fmaf(v, gamma[QK_+d],   beta[QK_+d]);
    float qo = qv, ko = kv;
    if (d < 32){
        int pd = d ^ 1;
        float vp = g_qkbuf[base + pd];
        float qp = fmaf(vp, gamma[pd],     beta[pd]);
        float kp = fmaf(vp, gamma[QK_+pd], beta[QK_+pd]);
        float invf = (float)(1.0 / pow(10000.0, (double)(2*(d>>1)) / 32.0));
        float fr = (float)s * invf;
        float cs = (float)cos((double)fr);
        float sn = (float)sin((double)fr);
        if ((d & 1) == 0){ qo = qv*cs - qp*sn; ko = kv*cs - kp*sn; }
        else             { qo = qv*cs + qp*sn; ko = kv*cs + kp*sn; }
    }
    g_q[base + d] = qo;
    g_k[base + d] = ko;
}

// ---------------- gate statistics ----------------
__global__ __launch_bounds__(256) void gate_hist_kernel(){
    int b = blockIdx.y;
    __shared__ int sh[129];
    __shared__ unsigned smax;
    int tid = threadIdx.x;
    for (int i = tid; i < 129; i += 256) sh[i] = 0;
    if (tid == 0) smax = 0u;
    __syncthreads();
    const int n = S_*H_;
    unsigned localmax = 0u;
    for (int i = blockIdx.x*256 + tid; i < n; i += gridDim.x*256){
        float gv = g_gate[(size_t)b*n + i];
        float a = fabsf(gv);
        int bin = (int)floorf(a); if (bin > 128) bin = 128;
        atomicAdd(&sh[bin], 1);
        unsigned u = __float_as_uint(gv);
        u = (u & 0x80000000u) ? ~u : (u | 0x80000000u);
        if (u > localmax) localmax = u;
    }
    atomicMax(&smax, localmax);
    __syncthreads();
    for (int i = tid; i < 129; i += 256) if (sh[i]) atomicAdd(&g_hist[b*129 + i], sh[i]);
    if (tid == 0) atomicMax(&g_gmax[b], smax);
}

__global__ void trim_kernel(){
    int b = threadIdx.x; if (b >= B_) return;
    unsigned u = g_gmax[b];
    u = (u & 0x80000000u) ? (u & 0x7FFFFFFFu) : ~u;
    float gmaxf = __uint_as_float(u);
    int gmax = (int)floorf(gmaxf);
    int cnt = 0, best = 0;
    for (int t = 128; t >= 1; t--){
        cnt += g_hist[b*129 + t];           // cnt = #(bin >= t)
        if (t <= gmax && cnt > 90000 && t > best) best = t;
    }
    g_trim[b] = best < 1 ? 1 : best;
}

__global__ __launch_bounds__(256) void counts_kernel(){
    int idx = blockIdx.x*256 + threadIdx.x;
    if (idx >= B_*100*120) return;
    int b = idx / 12000;
    int rem = idx % 12000;
    int i = rem / 120, j = rem % 120;
    float thr = (float)g_trim[b];
    const float* gb = g_gate + (size_t)b*S_*H_;
    int cnt = 0;
    #pragma unroll
    for (int r = 0; r < 4; r++)
        #pragma unroll
        for (int c = 0; c < 4; c++)
            cnt += (fabsf(gb[(i*5+r)*H_ + j*5+c]) >= thr);
    g_counts[idx] = (unsigned char)cnt;
    atomicMax(&g_cmax[b], cnt);
    atomicAdd(&g_hist2[b*17 + cnt], 1);
}

__global__ void t2_kernel(){
    int b = threadIdx.x; if (b >= B_) return;
    int cm = g_cmax[b];
    int cnt = 0, best = -1;
    for (int t = 16; t >= 1; t--){
        cnt += g_hist2[b*17 + t];           // cnt = #(counts >= t)
        if (t <= cm && cnt > 3600 && t > best) best = t;
    }
    g_t2[b] = (best >= 0) ? best : cm;
}

// ---------------- launch ----------------
extern "C" void kernel_launch(void* const* d_in, const int* in_sizes, int n_in,
                              void* d_out, int out_size){
    (void)in_sizes; (void)n_in; (void)out_size;
    const float* x       = (const float*)d_in[0];
    const float* mask2   = (const float*)d_in[1];
    const float* ln_g    = (const float*)d_in[2];
    const float* ln_b    = (const float*)d_in[3];
    const float* Wh      = (const float*)d_in[4];
    const float* bh      = (const float*)d_in[5];
    const float* Wqk     = (const float*)d_in[6];
    const float* bqk     = (const float*)d_in[7];
    const float* gamma   = (const float*)d_in[8];
    const float* beta    = (const float*)d_in[9];
    const float* rel_emb = (const float*)d_in[10];
    const float* Wout    = (const float*)d_in[11];
    const float* bout    = (const float*)d_in[12];
    float* out = (float*)d_out;

    float *nx, *q, *k, *v, *attn, *o;
    cudaGetSymbolAddress((void**)&nx,   g_nx);
    cudaGetSymbolAddress((void**)&q,    g_q);
    cudaGetSymbolAddress((void**)&k,    g_k);
    cudaGetSymbolAddress((void**)&v,    g_v);
    cudaGetSymbolAddress((void**)&attn, g_attn);
    cudaGetSymbolAddress((void**)&o,    g_o);

    const int M = B_*S_;   // 10000

    init_kernel<<<12, 256>>>(rel_emb);
    ln_kernel<<<M, 128>>>(x, ln_g, ln_b);

    // h = silu(nx @ Wh + bh)  -> v, gate
    sgemm_nn<<<dim3((2*H_+BN-1)/BN, (M+BM-1)/BM, 1), 256>>>(
        nx, Wh, M, 2*H_, D_, D_, 2*H_, 0L, 0L, EpiH{bh});

    // qk = silu(nx @ Wqk + bqk)
    sgemm_nn<<<dim3((QK_+BN-1)/BN, (M+BM-1)/BM, 1), 256>>>(
        nx, Wqk, M, QK_, D_, D_, QK_, 0L, 0L, EpiQK{bqk});

    rotary_kernel<<<M, 128>>>(gamma, beta);

    gate_hist_kernel<<<dim3(64, B_), 256>>>();
    trim_kernel<<<1, 32>>>();
    counts_kernel<<<(B_*100*120 + 255)/256, 256>>>();
    t2_kernel<<<1, 32>>>();

    // attn = (relu((q k^T + bias)/S))^2 * mask2   (batched NT)
    sgemm_nt<<<dim3((S_+BN-1)/BN, (S_+BM-1)/BM, B_), 256>>>(
        q, k, S_, S_, QK_, QK_, QK_, (long)S_*QK_, (long)S_*QK_, EpiScores{mask2});

    // o = gm * (attn @ v) * gate  (batched NN)
    sgemm_nn<<<dim3((H_+BN-1)/BN, (S_+BM-1)/BM, B_), 256>>>(
        attn, v, S_, H_, S_, S_, H_, (long)S_*S_, (long)S_*H_, EpiOut{});

    // out = o @ Wout + bout + x
    sgemm_nn<<<dim3((D_+BN-1)/BN, (M+BM-1)/BM, 1), 256>>>(
        o, Wout, M, D_, H_, H_, D_, 0L, 0L, EpiFinal{bout, x, out});
}

// round 2
// speedup vs baseline: 2.2092x; 2.2092x over previous
#include <cuda_runtime.h>
#include <cuda_bf16.h>
#include <math.h>

#define B_  20
#define S_  500
#define D_  300
#define H_  600
#define QK_ 128

typedef __nv_bfloat16 bf16;

// ---------------- scratch (device globals; no allocation) ----------------
__device__ bf16  g_nx_bf[B_*S_*D_];
__device__ float g_qkbuf[B_*S_*QK_];
__device__ bf16  g_q_bf[B_*S_*QK_];
__device__ bf16  g_k_bf[B_*S_*QK_];
__device__ bf16  g_v_bf[B_*S_*H_];
__device__ float g_gate[B_*S_*H_];
__device__ bf16  g_attn_bf[(size_t)B_*S_*S_];
__device__ bf16  g_o_bf[B_*S_*H_];
__device__ bf16  g_Wh_bf[D_*2*H_];
__device__ bf16  g_Wqk_bf[D_*QK_];
__device__ bf16  g_Wout_bf[H_*D_];
__device__ float g_bias[1024];
__device__ int   g_hist[B_*129];
__device__ unsigned g_gmax[B_];
__device__ int   g_trim[B_];
__device__ unsigned char g_counts[B_*100*120];
__device__ int   g_cmax[B_];
__device__ int   g_hist2[B_*17];
__device__ int   g_t2[B_];

// ---------------- accurate fp32 exp (robust to --use_fast_math) ----------------
__device__ __forceinline__ float my_expf(float x){
    x = fminf(fmaxf(x, -87.0f), 87.0f);
    float t = fmaf(x, 1.4426950408889634f, 12582912.0f);
    float n = t - 12582912.0f;
    float r = fmaf(n, -0.693359375f, x);
    r = fmaf(n, 2.1219444005469058e-4f, r);
    float p = 1.9841269841e-4f;
    p = fmaf(p, r, 1.3888888889e-3f);
    p = fmaf(p, r, 8.3333333333e-3f);
    p = fmaf(p, r, 4.1666666667e-2f);
    p = fmaf(p, r, 1.6666666667e-1f);
    p = fmaf(p, r, 0.5f);
    p = fmaf(p, r, 1.0f);
    p = fmaf(p, r, 1.0f);
    int e = (int)n;
    return p * __int_as_float((e + 127) << 23);
}
__device__ __forceinline__ float silu_f(float v){
    return v / (1.0f + my_expf(-v));
}

// ---------------- init: zero stats + build t5 bias table ----------------
__global__ void init_kernel(const float* __restrict__ rel_emb){
    int i = blockIdx.x * blockDim.x + threadIdx.x;
    if (i < B_*129) g_hist[i] = 0;
    if (i < B_*17)  g_hist2[i] = 0;
    if (i < B_)     { g_gmax[i] = 0u; g_cmax[i] = 0; }
    if (i < 999){
        int n = i - (S_-1);
        int ret = (n < 0) ? 16 : 0;
        int na = n < 0 ? -n : n;
        int bucket;
        if (na < 8) bucket = ret + na;
        else {
            float lnum = (float)log((double)na / 8.0);
            float lden = (float)log(16.0);
            float q = (float)((double)lnum / (double)lden);
            int vil = 8 + (int)(q * 8.0f);
            if (vil > 15) vil = 15;
            bucket = ret + vil;
        }
        g_bias[i] = rel_emb[bucket] * sqrtf(128.0f);
    }
}

__global__ void convert_weights(const float* __restrict__ Wh,
                                const float* __restrict__ Wqk,
                                const float* __restrict__ Wout){
    int i = blockIdx.x * blockDim.x + threadIdx.x;
    if (i < D_*2*H_) g_Wh_bf[i] = __float2bfloat16(Wh[i]);
    int j = i - D_*2*H_;
    if (j >= 0 && j < D_*QK_) g_Wqk_bf[j] = __float2bfloat16(Wqk[j]);
    int k2 = j - D_*QK_;
    if (k2 >= 0 && k2 < H_*D_) g_Wout_bf[k2] = __float2bfloat16(Wout[k2]);
}

// ---------------- LayerNorm + token-shift, emits bf16 nx ----------------
__global__ __launch_bounds__(128) void ln_kernel(const float* __restrict__ x,
                                                 const float* __restrict__ g,
                                                 const float* __restrict__ b){
    int bs = blockIdx.x;
    int batch = bs / S_, s = bs % S_;
    const float* xr = x + (size_t)bs * D_;
    __shared__ float red[128];
    int tid = threadIdx.x;
    float sum = 0.f;
    for (int i = tid; i < D_; i += 128) sum += xr[i];
    red[tid] = sum; __syncthreads();
    for (int off = 64; off > 0; off >>= 1){ if (tid < off) red[tid] += red[tid+off]; __syncthreads(); }
    float mean = red[0] * (1.0f / D_);
    __syncthreads();
    float vs = 0.f;
    for (int i = tid; i < D_; i += 128){ float d = xr[i]-mean; vs += d*d; }
    red[tid] = vs; __syncthreads();
    for (int off = 64; off > 0; off >>= 1){ if (tid < off) red[tid] += red[tid+off]; __syncthreads(); }
    float var = red[0] * (1.0f / D_);
    float inv = rsqrtf(var + 1e-5f);
    for (int i = tid; i < D_; i += 128){
        float val = (xr[i]-mean)*inv*g[i] + b[i];
        if (i < D_/2){
            if (s+1 < S_) g_nx_bf[((size_t)batch*S_ + s+1)*D_ + i] = __float2bfloat16(val);
        } else {
            g_nx_bf[(size_t)bs*D_ + i] = __float2bfloat16(val);
        }
    }
    if (s == 0){ for (int i = tid; i < D_/2; i += 128) g_nx_bf[(size_t)bs*D_ + i] = __float2bfloat16(0.f); }
}

// ================= bf16 tensor-core GEMM (mma.sync m16n8k16) =================
// CTA tile 128x64x32, 8 warps (4x2), warp tile 32x32.
#define BM 128
#define BN 64
#define BK 32
#define ASTR 40   // padded smem stride (conflict-free for frag loads)

__device__ __forceinline__ void mma16816(float c[4], const unsigned a[4], const unsigned b[2]){
    asm volatile("mma.sync.aligned.m16n8k16.row.col.f32.bf16.bf16.f32 "
                 "{%0,%1,%2,%3}, {%4,%5,%6,%7}, {%8,%9}, {%0,%1,%2,%3};"
                 : "+f"(c[0]), "+f"(c[1]), "+f"(c[2]), "+f"(c[3])
                 : "r"(a[0]), "r"(a[1]), "r"(a[2]), "r"(a[3]), "r"(b[0]), "r"(b[1]));
}

template<bool TRANS_B, class Epi>
__global__ __launch_bounds__(256) void gemm_bf(const bf16* __restrict__ A,
                                               const bf16* __restrict__ B,
                                               int M, int N, int K, int lda, int ldb,
                                               long sA, long sB, Epi epi){
    int bz = blockIdx.z;
    A += (size_t)bz * sA;  B += (size_t)bz * sB;
    __shared__ bf16 As[BM][ASTR];
    __shared__ bf16 Bs[BN][ASTR];   // stored N-major, K contiguous
    int row0 = blockIdx.y * BM, col0 = blockIdx.x * BN;
    int tid = threadIdx.x;
    int warp = tid >> 5, lane = tid & 31;
    int wm = warp >> 1, wn = warp & 1;
    int g = lane >> 2, t4 = lane & 3;

    float acc[2][4][4] = {};

    for (int k0 = 0; k0 < K; k0 += BK){
        // ---- load A tile: 128x32, 8-wide vector (4 bf16) per thread, 4 passes
        #pragma unroll
        for (int p = 0; p < 4; p++){
            int r = p*32 + (tid >> 3);
            int c4 = (tid & 7) * 4;
            int gr = row0 + r, gc = k0 + c4;
            uint2 val = make_uint2(0u, 0u);
            if (gr < M){
                if (gc + 4 <= K){
                    val = *reinterpret_cast<const uint2*>(A + (size_t)gr*lda + gc);
                } else if (gc < K){
                    __align__(8) bf16 tmp[4];
                    #pragma unroll
                    for (int j = 0; j < 4; j++)
                        tmp[j] = (gc + j < K) ? A[(size_t)gr*lda + gc + j] : __float2bfloat16(0.f);
                    val = *reinterpret_cast<uint2*>(tmp);
                }
            }
            *reinterpret_cast<uint2*>(&As[r][c4]) = val;
        }
        // ---- load B tile into Bs[n][k]
        if (TRANS_B){
            // B is [N][K] row-major: same pattern as A
            #pragma unroll
            for (int p = 0; p < 2; p++){
                int r = p*32 + (tid >> 3);      // n
                int c4 = (tid & 7) * 4;         // k
                int gn = col0 + r, gc = k0 + c4;
                uint2 val = make_uint2(0u, 0u);
                if (gn < N){
                    if (gc + 4 <= K){
                        val = *reinterpret_cast<const uint2*>(B + (size_t)gn*ldb + gc);
                    } else if (gc < K){
                        __align__(8) bf16 tmp[4];
                        #pragma unroll
                        for (int j = 0; j < 4; j++)
                            tmp[j] = (gc + j < K) ? B[(size_t)gn*ldb + gc + j] : __float2bfloat16(0.f);
                        val = *reinterpret_cast<uint2*>(tmp);
                    }
                }
                *reinterpret_cast<uint2*>(&Bs[r][c4]) = val;
            }
        } else {
            // B is [K][N] row-major: transpose into Bs[n][k], coalesced reads
            #pragma unroll
            for (int p = 0; p < 8; p++){
                int idx = p*256 + tid;
                int kk = idx >> 6;          // 0..31
                int nn = idx & 63;
                int gk = k0 + kk, gn = col0 + nn;
                bf16 v = (gk < K && gn < N) ? B[(size_t)gk*ldb + gn] : __float2bfloat16(0.f);
                Bs[nn][kk] = v;
            }
        }
        __syncthreads();

        #pragma unroll
        for (int ks = 0; ks < 2; ks++){
            unsigned a[2][4], bb[4][2];
            #pragma unroll
            for (int mi = 0; mi < 2; mi++){
                int row = wm*32 + mi*16;
                int kb = ks*16 + t4*2;
                a[mi][0] = *reinterpret_cast<const unsigned*>(&As[row + g    ][kb    ]);
                a[mi][1] = *reinterpret_cast<const unsigned*>(&As[row + g + 8][kb    ]);
                a[mi][2] = *reinterpret_cast<const unsigned*>(&As[row + g    ][kb + 8]);
                a[mi][3] = *reinterpret_cast<const unsigned*>(&As[row + g + 8][kb + 8]);
            }
            #pragma unroll
            for (int ni = 0; ni < 4; ni++){
                int col = wn*32 + ni*8;
                int kb = ks*16 + t4*2;
                bb[ni][0] = *reinterpret_cast<const unsigned*>(&Bs[col + g][kb    ]);
                bb[ni][1] = *reinterpret_cast<const unsigned*>(&Bs[col + g][kb + 8]);
            }
            #pragma unroll
            for (int mi = 0; mi < 2; mi++)
                #pragma unroll
                for (int ni = 0; ni < 4; ni++)
                    mma16816(acc[mi][ni], a[mi], bb[ni]);
        }
        __syncthreads();
    }

    // ---- epilogue
    #pragma unroll
    for (int mi = 0; mi < 2; mi++){
        #pragma unroll
        for (int ni = 0; ni < 4; ni++){
            int r = row0 + wm*32 + mi*16 + g;
            int c = col0 + wn*32 + ni*8 + t4*2;
            if (r < M){
                if (c     < N) epi(bz, r, c,     acc[mi][ni][0]);
                if (c + 1 < N) epi(bz, r, c + 1, acc[mi][ni][1]);
            }
            if (r + 8 < M){
                if (c     < N) epi(bz, r + 8, c,     acc[mi][ni][2]);
                if (c + 1 < N) epi(bz, r + 8, c + 1, acc[mi][ni][3]);
            }
        }
    }
}

// ---------------- epilogues ----------------
struct EpiH {
    const float* bh;
    __device__ void operator()(int, int r, int c, float acc) const {
        float s = silu_f(acc + bh[c]);
        if (c < H_) g_v_bf[(size_t)r*H_ + c] = __float2bfloat16(s);
        else        g_gate[(size_t)r*H_ + (c - H_)] = s;
    }
};
struct EpiQK {
    const float* bqk;
    __device__ void operator()(int, int r, int c, float acc) const {
        g_qkbuf[(size_t)r*QK_ + c] = silu_f(acc + bqk[c]);
    }
};
struct EpiScores {
    const float* mask2;
    __device__ void operator()(int bz, int r, int c, float acc) const {
        float val = acc + g_bias[r - c + (S_-1)];
        float t = fmaxf(val * (1.0f / S_), 0.0f);
        g_attn_bf[((size_t)bz*S_ + r)*S_ + c] = __float2bfloat16(t * t * mask2[r*S_ + c]);
    }
};
struct EpiOut {
    __device__ void operator()(int bz, int r, int c, float acc) const {
        int rr = r % 5, cc = c % 5;
        float m = 0.0f;
        if (rr != 4 && cc != 4){
            int cnt = g_counts[bz*12000 + (r/5)*120 + (c/5)];
            m = (cnt >= g_t2[bz]) ? 1.0f : 0.25f;
        }
        size_t idx = ((size_t)bz*S_ + r)*H_ + c;
        g_o_bf[idx] = __float2bfloat16(m * acc * g_gate[idx]);
    }
};
struct EpiFinal {
    const float* bout;
    const float* x;
    float* out;
    __device__ void operator()(int, int r, int c, float acc) const {
        out[(size_t)r*D_ + c] = acc + bout[c] + x[(size_t)r*D_ + c];
    }
};

// ---------------- rotary on q/k (emits bf16) ----------------
__global__ __launch_bounds__(128) void rotary_kernel(const float* __restrict__ gamma,
                                                     const float* __restrict__ beta){
    int bs = blockIdx.x;
    int s = bs % S_;
    int d = threadIdx.x;
    size_t base = (size_t)bs * QK_;
    float v  = g_qkbuf[base + d];
    float qv = fmaf(v, gamma[d],       beta[d]);
    float kv = fmaf(v, gamma[QK_+d],   beta[QK_+d]);
    float qo = qv, ko = kv;
    if (d < 32){
        int pd = d ^ 1;
        float vp = g_qkbuf[base + pd];
        float qp = fmaf(vp, gamma[pd],     beta[pd]);
        float kp = fmaf(vp, gamma[QK_+pd], beta[QK_+pd]);
        float invf = (float)(1.0 / pow(10000.0, (double)(2*(d>>1)) / 32.0));
        float fr = (float)s * invf;
        float cs = (float)cos((double)fr);
        float sn = (float)sin((double)fr);
        if ((d & 1) == 0){ qo = qv*cs - qp*sn; ko = kv*cs - kp*sn; }
        else             { qo = qv*cs + qp*sn; ko = kv*cs + kp*sn; }
    }
    g_q_bf[base + d] = __float2bfloat16(qo);
    g_k_bf[base + d] = __float2bfloat16(ko);
}

// ---------------- gate statistics ----------------
__global__ __launch_bounds__(256) void gate_hist_kernel(){
    int b = blockIdx.y;
    __shared__ int sh[129];
    __shared__ unsigned smax;
    int tid = threadIdx.x;
    for (int i = tid; i < 129; i += 256) sh[i] = 0;
    if (tid == 0) smax = 0u;
    __syncthreads();
    const int n = S_*H_;
    unsigned localmax = 0u;
    for (int i = blockIdx.x*256 + tid; i < n; i += gridDim.x*256){
        float gv = g_gate[(size_t)b*n + i];
        float a = fabsf(gv);
        int bin = (int)floorf(a); if (bin > 128) bin = 128;
        atomicAdd(&sh[bin], 1);
        unsigned u = __float_as_uint(gv);
        u = (u & 0x80000000u) ? ~u : (u | 0x80000000u);
        if (u > localmax) localmax = u;
    }
    atomicMax(&smax, localmax);
    __syncthreads();
    for (int i = tid; i < 129; i += 256) if (sh[i]) atomicAdd(&g_hist[b*129 + i], sh[i]);
    if (tid == 0) atomicMax(&g_gmax[b], smax);
}

__global__ void trim_kernel(){
    int b = threadIdx.x; if (b >= B_) return;
    unsigned u = g_gmax[b];
    u = (u & 0x80000000u) ? (u & 0x7FFFFFFFu) : ~u;
    float gmaxf = __uint_as_float(u);
    int gmax = (int)floorf(gmaxf);
    int cnt = 0, best = 0;
    for (int t = 128; t >= 1; t--){
        cnt += g_hist[b*129 + t];
        if (t <= gmax && cnt > 90000 && t > best) best = t;
    }
    g_trim[b] = best < 1 ? 1 : best;
}

__global__ __launch_bounds__(256) void counts_kernel(){
    int idx = blockIdx.x*256 + threadIdx.x;
    if (idx >= B_*100*120) return;
    int b = idx / 12000;
    int rem = idx % 12000;
    int i = rem / 120, j = rem % 120;
    float thr = (float)g_trim[b];
    const float* gb = g_gate + (size_t)b*S_*H_;
    int cnt = 0;
    #pragma unroll
    for (int r = 0; r < 4; r++)
        #pragma unroll
        for (int c = 0; c < 4; c++)
            cnt += (fabsf(gb[(i*5+r)*H_ + j*5+c]) >= thr);
    g_counts[idx] = (unsigned char)cnt;
    atomicMax(&g_cmax[b], cnt);
    atomicAdd(&g_hist2[b*17 + cnt], 1);
}

__global__ void t2_kernel(){
    int b = threadIdx.x; if (b >= B_) return;
    int cm = g_cmax[b];
    int cnt = 0, best = -1;
    for (int t = 16; t >= 1; t--){
        cnt += g_hist2[b*17 + t];
        if (t <= cm && cnt > 3600 && t > best) best = t;
    }
    g_t2[b] = (best >= 0) ? best : cm;
}

// ---------------- launch ----------------
extern "C" void kernel_launch(void* const* d_in, const int* in_sizes, int n_in,
                              void* d_out, int out_size){
    (void)in_sizes; (void)n_in; (void)out_size;
    const float* x       = (const float*)d_in[0];
    const float* mask2   = (const float*)d_in[1];
    const float* ln_g    = (const float*)d_in[2];
    const float* ln_b    = (const float*)d_in[3];
    const float* Wh      = (const float*)d_in[4];
    const float* bh      = (const float*)d_in[5];
    const float* Wqk     = (const float*)d_in[6];
    const float* bqk     = (const float*)d_in[7];
    const float* gamma   = (const float*)d_in[8];
    const float* beta    = (const float*)d_in[9];
    const float* rel_emb = (const float*)d_in[10];
    const float* Wout    = (const float*)d_in[11];
    const float* bout    = (const float*)d_in[12];
    float* out = (float*)d_out;

    bf16 *nx, *q, *k, *v, *attn, *o, *wh, *wqk, *wout;
    cudaGetSymbolAddress((void**)&nx,   g_nx_bf);
    cudaGetSymbolAddress((void**)&q,    g_q_bf);
    cudaGetSymbolAddress((void**)&k,    g_k_bf);
    cudaGetSymbolAddress((void**)&v,    g_v_bf);
    cudaGetSymbolAddress((void**)&attn, g_attn_bf);
    cudaGetSymbolAddress((void**)&o,    g_o_bf);
    cudaGetSymbolAddress((void**)&wh,   g_Wh_bf);
    cudaGetSymbolAddress((void**)&wqk,  g_Wqk_bf);
    cudaGetSymbolAddress((void**)&wout, g_Wout_bf);

    const int M = B_*S_;   // 10000

    init_kernel<<<12, 256>>>(rel_emb);
    convert_weights<<<(D_*2*H_ + D_*QK_ + H_*D_ + 255)/256, 256>>>(Wh, Wqk, Wout);
    ln_kernel<<<M, 128>>>(x, ln_g, ln_b);

    // h = silu(nx @ Wh + bh) -> v(bf16), gate(f32)
    gemm_bf<false><<<dim3((2*H_+BN-1)/BN, (M+BM-1)/BM, 1), 256>>>(
        nx, wh, M, 2*H_, D_, D_, 2*H_, 0L, 0L, EpiH{bh});

    // qk = silu(nx @ Wqk + bqk)
    gemm_bf<false><<<dim3((QK_+BN-1)/BN, (M+BM-1)/BM, 1), 256>>>(
        nx, wqk, M, QK_, D_, D_, QK_, 0L, 0L, EpiQK{bqk});

    rotary_kernel<<<M, 128>>>(gamma, beta);

    gate_hist_kernel<<<dim3(64, B_), 256>>>();
    trim_kernel<<<1, 32>>>();
    counts_kernel<<<(B_*100*120 + 255)/256, 256>>>();
    t2_kernel<<<1, 32>>>();

    // attn = (relu((q k^T + bias)/S))^2 * mask2   (batched NT)
    gemm_bf<true><<<dim3((S_+BN-1)/BN, (S_+BM-1)/BM, B_), 256>>>(
        q, k, S_, S_, QK_, QK_, QK_, (long)S_*QK_, (long)S_*QK_, EpiScores{mask2});

    // o = gm * (attn @ v) * gate  (batched NN)
    gemm_bf<false><<<dim3((H_+BN-1)/BN, (S_+BM-1)/BM, B_), 256>>>(
        attn, v, S_, H_, S_, S_, H_, (long)S_*S_, (long)S_*H_, EpiOut{});

    // out = o @ Wout + bout + x
    gemm_bf<false><<<dim3((D_+BN-1)/BN, (M+BM-1)/BM, 1), 256>>>(
        o, wout, M, D_, H_, H_, D_, 0L, 0L, EpiFinal{bout, x, out});
}

// round 3
// speedup vs baseline: 3.2276x; 1.4610x over previous
#include <cuda_runtime.h>
#include <cuda_bf16.h>
#include <math.h>

#define B_  20
#define S_  500
#define D_  300
#define H_  600
#define QK_ 128
#define NXS 304      // nx row stride (16B aligned)
#define ATS 512      // attn row stride
#define WOS 304      // Wout row stride

typedef __nv_bfloat16 bf16;

// ---------------- scratch (device globals; no allocation) ----------------
__device__ __align__(16) bf16  g_nx_bf[B_*S_*NXS];
__device__ __align__(16) bf16  g_q_bf[B_*S_*QK_];
__device__ __align__(16) bf16  g_k_bf[B_*S_*QK_];
__device__ __align__(16) bf16  g_v_bf[B_*S_*H_];
__device__ float g_gate[B_*S_*H_];
__device__ __align__(16) bf16  g_attn_bf[(size_t)B_*S_*ATS];
__device__ __align__(16) bf16  g_o_bf[B_*S_*H_];
__device__ __align__(16) bf16  g_Wh_bf[D_*2*H_];
__device__ __align__(16) bf16  g_Wqk_bf[D_*QK_];
__device__ __align__(16) bf16  g_Wout_bf[H_*WOS];
__device__ float g_bias[1024];
__device__ float2 g_rot[S_*16];
__device__ int   g_hist[B_*129];
__device__ unsigned g_gmax[B_];
__device__ int   g_trim[B_];
__device__ unsigned char g_counts[B_*100*120];
__device__ int   g_cmax[B_];
__device__ int   g_hist2[B_*17];
__device__ int   g_t2[B_];

// ---------------- accurate fp32 exp (robust to fast-math) ----------------
__device__ __forceinline__ float my_expf(float x){
    x = fminf(fmaxf(x, -87.0f), 87.0f);
    float t = fmaf(x, 1.4426950408889634f, 12582912.0f);
    float n = t - 12582912.0f;
    float r = fmaf(n, -0.693359375f, x);
    r = fmaf(n, 2.1219444005469058e-4f, r);
    float p = 1.9841269841e-4f;
    p = fmaf(p, r, 1.3888888889e-3f);
    p = fmaf(p, r, 8.3333333333e-3f);
    p = fmaf(p, r, 4.1666666667e-2f);
    p = fmaf(p, r, 1.6666666667e-1f);
    p = fmaf(p, r, 0.5f);
    p = fmaf(p, r, 1.0f);
    p = fmaf(p, r, 1.0f);
    int e = (int)n;
    return p * __int_as_float((e + 127) << 23);
}
__device__ __forceinline__ float silu_f(float v){
    return v * __fdividef(1.0f, 1.0f + my_expf(-v));
}

// ---------------- init: zero stats + bias table + rotary table ----------------
__global__ void init_kernel(const float* __restrict__ rel_emb){
    int i = blockIdx.x * blockDim.x + threadIdx.x;
    if (i < B_*129) g_hist[i] = 0;
    if (i < B_*17)  g_hist2[i] = 0;
    if (i < B_)     { g_gmax[i] = 0u; g_cmax[i] = 0; }
    if (i < 999){
        int n = i - (S_-1);
        int ret = (n < 0) ? 16 : 0;
        int na = n < 0 ? -n : n;
        int bucket;
        if (na < 8) bucket = ret + na;
        else {
            float lnum = (float)log((double)na / 8.0);
            float lden = (float)log(16.0);
            float q = (float)((double)lnum / (double)lden);
            int vil = 8 + (int)(q * 8.0f);
            if (vil > 15) vil = 15;
            bucket = ret + vil;
        }
        g_bias[i] = rel_emb[bucket] * sqrtf(128.0f);
    }
    if (i < S_*16){
        int s = i >> 4, f = i & 15;
        double inv = pow(10000.0, -(double)(2*f)/32.0);
        float fr = (float)s * (float)inv;
        g_rot[i] = make_float2((float)cos((double)fr), (float)sin((double)fr));
    }
}

__global__ void convert_weights(const float* __restrict__ Wh,
                                const float* __restrict__ Wqk,
                                const float* __restrict__ Wout){
    int i = blockIdx.x * blockDim.x + threadIdx.x;
    if (i < D_*2*H_) g_Wh_bf[i] = __float2bfloat16(Wh[i]);
    int j = i - D_*2*H_;
    if (j >= 0 && j < D_*QK_) g_Wqk_bf[j] = __float2bfloat16(Wqk[j]);
    int k2 = j - D_*QK_;
    if (k2 >= 0 && k2 < H_*D_){
        int row = k2 / D_, col = k2 % D_;
        g_Wout_bf[row*WOS + col] = __float2bfloat16(Wout[k2]);
    }
}

// ---------------- LayerNorm + token-shift, emits bf16 nx (stride NXS) ----------------
__global__ __launch_bounds__(128) void ln_kernel(const float* __restrict__ x,
                                                 const float* __restrict__ g,
                                                 const float* __restrict__ b){
    int bs = blockIdx.x;
    int batch = bs / S_, s = bs % S_;
    const float* xr = x + (size_t)bs * D_;
    __shared__ float red[128];
    int tid = threadIdx.x;
    float sum = 0.f;
    for (int i = tid; i < D_; i += 128) sum += xr[i];
    red[tid] = sum; __syncthreads();
    for (int off = 64; off > 0; off >>= 1){ if (tid < off) red[tid] += red[tid+off]; __syncthreads(); }
    float mean = red[0] * (1.0f / D_);
    __syncthreads();
    float vs = 0.f;
    for (int i = tid; i < D_; i += 128){ float d = xr[i]-mean; vs += d*d; }
    red[tid] = vs; __syncthreads();
    for (int off = 64; off > 0; off >>= 1){ if (tid < off) red[tid] += red[tid+off]; __syncthreads(); }
    float var = red[0] * (1.0f / D_);
    float inv = rsqrtf(var + 1e-5f);
    for (int i = tid; i < D_; i += 128){
        float val = (xr[i]-mean)*inv*g[i] + b[i];
        if (i < D_/2){
            if (s+1 < S_) g_nx_bf[((size_t)batch*S_ + s+1)*NXS + i] = __float2bfloat16(val);
        } else {
            g_nx_bf[(size_t)bs*NXS + i] = __float2bfloat16(val);
        }
    }
    if (s == 0){ for (int i = tid; i < D_/2; i += 128) g_nx_bf[(size_t)bs*NXS + i] = __float2bfloat16(0.f); }
}

// ================= bf16 mma.sync GEMM: cp.async 2-stage + ldmatrix =================
#define BM 128
#define BN 64
#define BK 32
#define ASTR 40        // As / Bs_nt element stride (conflict-free, 16B aligned rows)
#define BSTR_NN 72     // Bs_nn element stride
#define A_ST (BM*ASTR)     // 5120 elems per stage
#define B_ST 2560          // max(64*40, 32*72)

__device__ __forceinline__ void mma16816(float c[4], const unsigned a[4], const unsigned b[2]){
    asm volatile("mma.sync.aligned.m16n8k16.row.col.f32.bf16.bf16.f32 "
                 "{%0,%1,%2,%3}, {%4,%5,%6,%7}, {%8,%9}, {%0,%1,%2,%3};"
                 : "+f"(c[0]), "+f"(c[1]), "+f"(c[2]), "+f"(c[3])
                 : "r"(a[0]), "r"(a[1]), "r"(a[2]), "r"(a[3]), "r"(b[0]), "r"(b[1]));
}
__device__ __forceinline__ void cp16(unsigned dst, const void* src, int bytes){
    asm volatile("cp.async.ca.shared.global [%0], [%1], 16, %2;" :: "r"(dst), "l"(src), "r"(bytes));
}
__device__ __forceinline__ void cp_commit(){ asm volatile("cp.async.commit_group;"); }
__device__ __forceinline__ void cp_wait1(){ asm volatile("cp.async.wait_group 1;"); }

template<bool TRANS_B, class Epi>
__global__ __launch_bounds__(256, 2) void gemm_bf(const bf16* __restrict__ A,
        const bf16* __restrict__ Bm, int M, int N, int K, int lda, int ldb,
        long sA, long sB, Epi epi)
{
    int bz = blockIdx.z;
    A  += (size_t)bz * sA;
    Bm += (size_t)bz * sB;
    __shared__ bf16 smA[2][A_ST];
    __shared__ bf16 smB[2][B_ST];
    int row0 = blockIdx.y*BM, col0 = blockIdx.x*BN;
    int tid = threadIdx.x, warp = tid>>5, lane = tid&31;
    int wm = warp>>1, wn = warp&1;
    int g = lane>>2, t4 = lane&3;

    unsigned aS = (unsigned)__cvta_generic_to_shared(&smA[0][0]);
    unsigned bS = (unsigned)__cvta_generic_to_shared(&smB[0][0]);

    // producer thread coordinates
    int ar = tid>>2;            // A tile row (passes: ar, ar+64)
    int ak = (tid&3)*8;         // A tile k col
    int br_nt = tid>>2, bk_nt = (tid&3)*8;   // TRANS: n-row, k-col
    int br_nn = tid>>3, bk_nn = (tid&7)*8;   // NN:    k-row, n-col

    auto load_stage = [&](int st, int k0){
        #pragma unroll
        for (int p = 0; p < 2; p++){
            int r = ar + p*64;
            int gr = row0 + r, gk = k0 + ak;
            const bf16* src = A;
            int bytes = 0;
            if (gr < M){
                int rem = (K - gk)*2;
                bytes = rem < 0 ? 0 : (rem > 16 ? 16 : rem);
                if (bytes > 0) src = A + (size_t)gr*lda + gk;
            }
            cp16(aS + (st*A_ST + r*ASTR + ak)*2, src, bytes);
        }
        if (TRANS_B){
            int gn = col0 + br_nt, gk = k0 + bk_nt;
            const bf16* src = Bm; int bytes = 0;
            if (gn < N){
                int rem = (K - gk)*2;
                bytes = rem < 0 ? 0 : (rem > 16 ? 16 : rem);
                if (bytes > 0) src = Bm + (size_t)gn*ldb + gk;
            }
            cp16(bS + (st*B_ST + br_nt*ASTR + bk_nt)*2, src, bytes);
        } else {
            int gk = k0 + br_nn, gn = col0 + bk_nn;
            const bf16* src = Bm; int bytes = 0;
            if (gk < K){
                int rem = (N - gn)*2;
                bytes = rem < 0 ? 0 : (rem > 16 ? 16 : rem);
                if (bytes > 0) src = Bm + (size_t)gk*ldb + gn;
            }
            cp16(bS + (st*B_ST + br_nn*BSTR_NN + bk_nn)*2, src, bytes);
        }
    };

    float acc[2][4][4] = {};

    load_stage(0, 0);
    cp_commit();

    int nk = (K + BK - 1)/BK;
    for (int it = 0; it < nk; it++){
        if (it + 1 < nk) load_stage((it+1)&1, (it+1)*BK);
        cp_commit();
        cp_wait1();
        __syncthreads();
        int st = it & 1;
        unsigned aBase = aS + st*A_ST*2;
        unsigned bBase = bS + st*B_ST*2;
        unsigned aAddr = aBase + (unsigned)(((wm*32 + (lane&15))*ASTR + (lane>>4)*8)*2);
        #pragma unroll
        for (int ks = 0; ks < 2; ks++){
            unsigned ra[2][4];
            #pragma unroll
            for (int mi = 0; mi < 2; mi++){
                unsigned ad = aAddr + (unsigned)((mi*16*ASTR + ks*16)*2);
                asm volatile("ldmatrix.sync.aligned.m8n8.x4.shared.b16 {%0,%1,%2,%3}, [%4];"
                    : "=r"(ra[mi][0]),"=r"(ra[mi][1]),"=r"(ra[mi][2]),"=r"(ra[mi][3]) : "r"(ad));
            }
            unsigned rb[4][2];
            if (TRANS_B){
                int m = lane>>3, i = lane&7;
                int rowoff = i + ((m>>1)<<3);
                int kcoff  = (m&1)<<3;
                #pragma unroll
                for (int h = 0; h < 2; h++){
                    unsigned bd = bBase + (unsigned)(((wn*32 + h*16 + rowoff)*ASTR + ks*16 + kcoff)*2);
                    unsigned r0,r1,r2,r3;
                    asm volatile("ldmatrix.sync.aligned.m8n8.x4.shared.b16 {%0,%1,%2,%3}, [%4];"
                        : "=r"(r0),"=r"(r1),"=r"(r2),"=r"(r3) : "r"(bd));
                    rb[h*2][0]=r0; rb[h*2][1]=r1; rb[h*2+1][0]=r2; rb[h*2+1][1]=r3;
                }
            } else {
                int m = lane>>3, i = lane&7;
                int krow = i + ((m&1)<<3);
                int ncoff = (m>>1)<<3;
                #pragma unroll
                for (int h = 0; h < 2; h++){
                    unsigned bd = bBase + (unsigned)(((ks*16 + krow)*BSTR_NN + wn*32 + h*16 + ncoff)*2);
                    unsigned r0,r1,r2,r3;
                    asm volatile("ldmatrix.sync.aligned.m8n8.x4.trans.shared.b16 {%0,%1,%2,%3}, [%4];"
                        : "=r"(r0),"=r"(r1),"=r"(r2),"=r"(r3) : "r"(bd));
                    rb[h*2][0]=r0; rb[h*2][1]=r1; rb[h*2+1][0]=r2; rb[h*2+1][1]=r3;
                }
            }
            #pragma unroll
            for (int mi = 0; mi < 2; mi++)
                #pragma unroll
                for (int ni = 0; ni < 4; ni++)
                    mma16816(acc[mi][ni], ra[mi], rb[ni]);
        }
        __syncthreads();
    }

    #pragma unroll
    for (int mi = 0; mi < 2; mi++)
        #pragma unroll
        for (int ni = 0; ni < 4; ni++){
            int c = col0 + wn*32 + ni*8 + t4*2;
            int nv = (c + 1 < N) ? 2 : (c < N ? 1 : 0);
            if (nv){
                int r = row0 + wm*32 + mi*16 + g;
                if (r < M)     epi(bz, r,     c, acc[mi][ni][0], acc[mi][ni][1], nv);
                if (r + 8 < M) epi(bz, r + 8, c, acc[mi][ni][2], acc[mi][ni][3], nv);
            }
        }
}

// ---------------- epilogues (pair interface) ----------------
struct EpiH {
    const float* bh;
    __device__ void operator()(int, int r, int c, float a0, float a1, int nv) const {
        float s0 = silu_f(a0 + bh[c]);
        if (c < H_) g_v_bf[(size_t)r*H_ + c] = __float2bfloat16(s0);
        else        g_gate[(size_t)r*H_ + c - H_] = s0;
        if (nv == 2){
            float s1 = silu_f(a1 + bh[c+1]);
            if (c+1 < H_) g_v_bf[(size_t)r*H_ + c+1] = __float2bfloat16(s1);
            else          g_gate[(size_t)r*H_ + c+1 - H_] = s1;
        }
    }
};
struct EpiQK {   // fused silu + gamma/beta + rotary
    const float* bqk; const float* gamma; const float* beta;
    __device__ void operator()(int, int r, int c, float a0, float a1, int) const {
        int s = r % S_;
        float s0 = silu_f(a0 + bqk[c]);
        float s1 = silu_f(a1 + bqk[c+1]);
        float q0 = fmaf(s0, gamma[c],       beta[c]);
        float q1 = fmaf(s1, gamma[c+1],     beta[c+1]);
        float k0 = fmaf(s0, gamma[QK_+c],   beta[QK_+c]);
        float k1 = fmaf(s1, gamma[QK_+c+1], beta[QK_+c+1]);
        if (c < 32){
            float2 cs = g_rot[s*16 + (c>>1)];
            float q0n = q0*cs.x - q1*cs.y, q1n = q1*cs.x + q0*cs.y;
            float k0n = k0*cs.x - k1*cs.y, k1n = k1*cs.x + k0*cs.y;
            q0=q0n; q1=q1n; k0=k0n; k1=k1n;
        }
        size_t base = (size_t)r*QK_;
        g_q_bf[base+c]   = __float2bfloat16(q0);
        g_q_bf[base+c+1] = __float2bfloat16(q1);
        g_k_bf[base+c]   = __float2bfloat16(k0);
        g_k_bf[base+c+1] = __float2bfloat16(k1);
    }
};
struct EpiScores {
    const float* mask2;
    __device__ void operator()(int bz, int r, int c, float a0, float a1, int nv) const {
        size_t rowb = ((size_t)bz*S_ + r)*ATS;
        float v0 = a0 + g_bias[r - c + (S_-1)];
        float t0 = fmaxf(v0 * (1.0f/S_), 0.f);
        g_attn_bf[rowb + c] = __float2bfloat16(t0*t0*mask2[r*S_ + c]);
        if (nv == 2){
            float v1 = a1 + g_bias[r - c - 1 + (S_-1)];
            float t1 = fmaxf(v1 * (1.0f/S_), 0.f);
            g_attn_bf[rowb + c + 1] = __float2bfloat16(t1*t1*mask2[r*S_ + c + 1]);
        }
    }
};
struct EpiOut {
    __device__ __forceinline__ float gm(int bz, int r, int c) const {
        int rr = r % 5, cc = c % 5;
        if (rr == 4 || cc == 4) return 0.0f;
        int cnt = g_counts[bz*12000 + (r/5)*120 + (c/5)];
        return (cnt >= g_t2[bz]) ? 1.0f : 0.25f;
    }
    __device__ void operator()(int bz, int r, int c, float a0, float a1, int nv) const {
        size_t idx = ((size_t)bz*S_ + r)*H_ + c;
        g_o_bf[idx] = __float2bfloat16(gm(bz,r,c) * a0 * g_gate[idx]);
        if (nv == 2)
            g_o_bf[idx+1] = __float2bfloat16(gm(bz,r,c+1) * a1 * g_gate[idx+1]);
    }
};
struct EpiFinal {
    const float* bout; const float* x; float* out;
    __device__ void operator()(int, int r, int c, float a0, float a1, int nv) const {
        out[(size_t)r*D_ + c] = a0 + bout[c] + x[(size_t)r*D_ + c];
        if (nv == 2)
            out[(size_t)r*D_ + c + 1] = a1 + bout[c+1] + x[(size_t)r*D_ + c + 1];
    }
};

// ---------------- gate statistics ----------------
__global__ __launch_bounds__(256) void gate_hist_kernel(){
    int b = blockIdx.y;
    __shared__ int sh[129];
    __shared__ unsigned smax;
    int tid = threadIdx.x, lane = tid & 31;
    for (int i = tid; i < 129; i += 256) sh[i] = 0;
    if (tid == 0) smax = 0u;
    __syncthreads();
    const int n = S_*H_;
    unsigned localmax = 0u;
    int stride = gridDim.x * 256;
    for (int base = blockIdx.x*256; base < n; base += stride){
        int i = base + tid;
        bool valid = i < n;
        int bin = 130;
        if (valid){
            float gv = g_gate[(size_t)b*n + i];
            float a = fabsf(gv);
            bin = (int)floorf(a); if (bin > 128) bin = 128;
            unsigned u = __float_as_uint(gv);
            u = (u & 0x80000000u) ? ~u : (u | 0x80000000u);
            if (u > localmax) localmax = u;
        }
        unsigned m0 = __ballot_sync(0xffffffffu, bin == 0);
        if (valid && bin != 0) atomicAdd(&sh[bin], 1);
        if (lane == 0 && m0)   atomicAdd(&sh[0], __popc(m0));
    }
    atomicMax(&smax, localmax);
    __syncthreads();
    for (int i = tid; i < 129; i += 256) if (sh[i]) atomicAdd(&g_hist[b*129 + i], sh[i]);
    if (tid == 0) atomicMax(&g_gmax[b], smax);
}

__global__ void trim_kernel(){
    int b = threadIdx.x; if (b >= B_) return;
    unsigned u = g_gmax[b];
    u = (u & 0x80000000u) ? (u & 0x7FFFFFFFu) : ~u;
    float gmaxf = __uint_as_float(u);
    int gmax = (int)floorf(gmaxf);
    int cnt = 0, best = 0;
    for (int t = 128; t >= 1; t--){
        cnt += g_hist[b*129 + t];
        if (t <= gmax && cnt > 90000 && t > best) best = t;
    }
    g_trim[b] = best < 1 ? 1 : best;
}

__global__ __launch_bounds__(256) void counts_kernel(){
    int idx = blockIdx.x*256 + threadIdx.x;
    if (idx >= B_*100*120) return;
    int b = idx / 12000;
    int rem = idx % 12000;
    int i = rem / 120, j = rem % 120;
    float thr = (float)g_trim[b];
    const float* gb = g_gate + (size_t)b*S_*H_;
    int cnt = 0;
    #pragma unroll
    for (int r = 0; r < 4; r++)
        #pragma unroll
        for (int c = 0; c < 4; c++)
            cnt += (fabsf(gb[(i*5+r)*H_ + j*5+c]) >= thr);
    g_counts[idx] = (unsigned char)cnt;
    atomicMax(&g_cmax[b], cnt);
    atomicAdd(&g_hist2[b*17 + cnt], 1);
}

__global__ void t2_kernel(){
    int b = threadIdx.x; if (b >= B_) return;
    int cm = g_cmax[b];
    int cnt = 0, best = -1;
    for (int t = 16; t >= 1; t--){
        cnt += g_hist2[b*17 + t];
        if (t <= cm && cnt > 3600 && t > best) best = t;
    }
    g_t2[b] = (best >= 0) ? best : cm;
}

// ---------------- launch ----------------
extern "C" void kernel_launch(void* const* d_in, const int* in_sizes, int n_in,
                              void* d_out, int out_size){
    (void)in_sizes; (void)n_in; (void)out_size;
    const float* x       = (const float*)d_in[0];
    const float* mask2   = (const float*)d_in[1];
    const float* ln_g    = (const float*)d_in[2];
    const float* ln_b    = (const float*)d_in[3];
    const float* Wh      = (const float*)d_in[4];
    const float* bh      = (const float*)d_in[5];
    const float* Wqk     = (const float*)d_in[6];
    const float* bqk     = (const float*)d_in[7];
    const float* gamma   = (const float*)d_in[8];
    const float* beta    = (const float*)d_in[9];
    const float* rel_emb = (const float*)d_in[10];
    const float* Wout    = (const float*)d_in[11];
    const float* bout    = (const float*)d_in[12];
    float* out = (float*)d_out;

    bf16 *nx, *q, *k, *v, *attn, *o, *wh, *wqk, *wout;
    cudaGetSymbolAddress((void**)&nx,   g_nx_bf);
    cudaGetSymbolAddress((void**)&q,    g_q_bf);
    cudaGetSymbolAddress((void**)&k,    g_k_bf);
    cudaGetSymbolAddress((void**)&v,    g_v_bf);
    cudaGetSymbolAddress((void**)&attn, g_attn_bf);
    cudaGetSymbolAddress((void**)&o,    g_o_bf);
    cudaGetSymbolAddress((void**)&wh,   g_Wh_bf);
    cudaGetSymbolAddress((void**)&wqk,  g_Wqk_bf);
    cudaGetSymbolAddress((void**)&wout, g_Wout_bf);

    const int M = B_*S_;   // 10000

    init_kernel<<<40, 256>>>(rel_emb);
    convert_weights<<<(D_*2*H_ + D_*QK_ + H_*D_ + 255)/256, 256>>>(Wh, Wqk, Wout);
    ln_kernel<<<M, 128>>>(x, ln_g, ln_b);

    // h = silu(nx @ Wh + bh) -> v(bf16), gate(f32)
    gemm_bf<false><<<dim3((2*H_+BN-1)/BN, (M+BM-1)/BM, 1), 256>>>(
        nx, wh, M, 2*H_, D_, NXS, 2*H_, 0L, 0L, EpiH{bh});

    // qk -> fused silu + gamma/beta + rotary -> q,k (bf16)
    gemm_bf<false><<<dim3((QK_+BN-1)/BN, (M+BM-1)/BM, 1), 256>>>(
        nx, wqk, M, QK_, D_, NXS, QK_, 0L, 0L, EpiQK{bqk, gamma, beta});

    gate_hist_kernel<<<dim3(120, B_), 256>>>();
    trim_kernel<<<1, 32>>>();
    counts_kernel<<<(B_*100*120 + 255)/256, 256>>>();
    t2_kernel<<<1, 32>>>();

    // attn = (relu((q k^T + bias)/S))^2 * mask2   (batched NT)
    gemm_bf<true><<<dim3((S_+BN-1)/BN, (S_+BM-1)/BM, B_), 256>>>(
        q, k, S_, S_, QK_, QK_, QK_, (long)S_*QK_, (long)S_*QK_, EpiScores{mask2});

    // o = gm * (attn @ v) * gate  (batched NN)
    gemm_bf<false><<<dim3((H_+BN-1)/BN, (S_+BM-1)/BM, B_), 256>>>(
        attn, v, S_, H_, S_, ATS, H_, (long)S_*ATS, (long)S_*H_, EpiOut{});

    // out = o @ Wout + bout + x
    gemm_bf<false><<<dim3((D_+BN-1)/BN, (M+BM-1)/BM, 1), 256>>>(
        o, wout, M, D_, H_, H_, WOS, 0L, 0L, EpiFinal{bout, x, out});
}

// round 4
// speedup vs baseline: 3.3437x; 1.0360x over previous
#include <cuda_runtime.h>
#include <cuda_bf16.h>
#include <math.h>

#define B_  20
#define S_  500
#define D_  300
#define H_  600
#define QK_ 128
#define NXS 304      // nx row stride (16B aligned)
#define ATS 512      // attn row stride
#define WOS 304      // Wout row stride

typedef __nv_bfloat16 bf16;

// ---------------- scratch (device globals; no allocation) ----------------
__device__ __align__(16) bf16  g_nx_bf[B_*S_*NXS];
__device__ __align__(16) bf16  g_q_bf[B_*S_*QK_];
__device__ __align__(16) bf16  g_k_bf[B_*S_*QK_];
__device__ __align__(16) bf16  g_v_bf[B_*S_*H_];
__device__ float g_gate[B_*S_*H_];
__device__ __align__(16) bf16  g_attn_bf[(size_t)B_*S_*ATS];
__device__ __align__(16) bf16  g_o_bf[B_*S_*H_];
__device__ __align__(16) bf16  g_Wh_bf[D_*2*H_];
__device__ __align__(16) bf16  g_Wqk_bf[D_*QK_];
__device__ __align__(16) bf16  g_Wout_bf[H_*WOS];
__device__ float g_bias[1024];
__device__ float2 g_rot[S_*16];
__device__ int   g_hist[B_*129];
__device__ unsigned g_gmax[B_];
__device__ int   g_trim[B_];
__device__ unsigned char g_counts[B_*100*120];
__device__ int   g_cmax[B_];
__device__ int   g_hist2[B_*17];
__device__ int   g_t2[B_];

// ---------------- accurate fp32 exp (robust to fast-math) ----------------
__device__ __forceinline__ float my_expf(float x){
    x = fminf(fmaxf(x, -87.0f), 87.0f);
    float t = fmaf(x, 1.4426950408889634f, 12582912.0f);
    float n = t - 12582912.0f;
    float r = fmaf(n, -0.693359375f, x);
    r = fmaf(n, 2.1219444005469058e-4f, r);
    float p = 1.9841269841e-4f;
    p = fmaf(p, r, 1.3888888889e-3f);
    p = fmaf(p, r, 8.3333333333e-3f);
    p = fmaf(p, r, 4.1666666667e-2f);
    p = fmaf(p, r, 1.6666666667e-1f);
    p = fmaf(p, r, 0.5f);
    p = fmaf(p, r, 1.0f);
    p = fmaf(p, r, 1.0f);
    int e = (int)n;
    return p * __int_as_float((e + 127) << 23);
}
__device__ __forceinline__ float silu_f(float v){
    return v * __fdividef(1.0f, 1.0f + my_expf(-v));
}

// ------------- setup: zero stats, bias+rot tables, weight conversion -------------
__global__ void setup_kernel(const float* __restrict__ rel_emb,
                             const float* __restrict__ Wh,
                             const float* __restrict__ Wqk,
                             const float* __restrict__ Wout){
    int i = blockIdx.x * blockDim.x + threadIdx.x;
    if (i < B_*129) g_hist[i] = 0;
    if (i < B_*17)  g_hist2[i] = 0;
    if (i < B_)     { g_gmax[i] = 0u; g_cmax[i] = 0; }
    if (i < 999){
        int n = i - (S_-1);
        int ret = (n < 0) ? 16 : 0;
        int na = n < 0 ? -n : n;
        int bucket;
        if (na < 8) bucket = ret + na;
        else {
            float lnum = (float)log((double)na / 8.0);
            float lden = (float)log(16.0);
            float q = (float)((double)lnum / (double)lden);
            int vil = 8 + (int)(q * 8.0f);
            if (vil > 15) vil = 15;
            bucket = ret + vil;
        }
        g_bias[i] = rel_emb[bucket] * sqrtf(128.0f);
    }
    if (i < S_*16){
        int s = i >> 4, f = i & 15;
        double inv = pow(10000.0, -(double)(2*f)/32.0);
        float fr = (float)s * (float)inv;
        g_rot[i] = make_float2((float)cos((double)fr), (float)sin((double)fr));
    }
    if (i < D_*2*H_) g_Wh_bf[i] = __float2bfloat16(Wh[i]);
    if (i < D_*QK_)  g_Wqk_bf[i] = __float2bfloat16(Wqk[i]);
    if (i < H_*D_){
        int row = i / D_, col = i % D_;
        g_Wout_bf[row*WOS + col] = __float2bfloat16(Wout[i]);
    }
}

// ---------------- LayerNorm, warp-per-row, single-pass ----------------
__global__ __launch_bounds__(128) void ln_kernel(const float* __restrict__ x,
                                                 const float* __restrict__ g,
                                                 const float* __restrict__ b){
    int w = threadIdx.x >> 5, lane = threadIdx.x & 31;
    int bs = blockIdx.x * 4 + w;
    int batch = bs / S_, s = bs % S_;
    const float* xr = x + (size_t)bs * D_;
    float xv[10];
    float sum = 0.f, ss = 0.f;
    #pragma unroll
    for (int j = 0; j < 10; j++){
        int i = j*32 + lane;
        float v = (i < D_) ? xr[i] : 0.f;
        xv[j] = v; sum += v; ss = fmaf(v, v, ss);
    }
    #pragma unroll
    for (int o = 16; o; o >>= 1){
        sum += __shfl_xor_sync(0xffffffffu, sum, o);
        ss  += __shfl_xor_sync(0xffffffffu, ss,  o);
    }
    float mean = sum * (1.0f / D_);
    float var  = ss * (1.0f / D_) - mean*mean;
    float inv  = rsqrtf(var + 1e-5f);
    size_t selfRow = (size_t)bs * NXS;
    size_t nextRow = ((size_t)batch*S_ + s + 1) * NXS;
    #pragma unroll
    for (int j = 0; j < 10; j++){
        int i = j*32 + lane;
        if (i >= D_) break;
        float val = (xv[j]-mean)*inv*g[i] + b[i];
        if (i < D_/2){
            if (s+1 < S_) g_nx_bf[nextRow + i] = __float2bfloat16(val);
        } else {
            g_nx_bf[selfRow + i] = __float2bfloat16(val);
        }
    }
    if (s == 0){
        #pragma unroll
        for (int j = 0; j < 5; j++){
            int i = j*32 + lane;
            if (i < D_/2) g_nx_bf[selfRow + i] = __float2bfloat16(0.f);
        }
    }
}

// ========== bf16 mma.sync GEMM: 3-stage cp.async, 1 sync/iter, hoisted addrs ==========
#define BM 128
#define BN 64
#define BK 32
#define ASTR 40        // As / Bs_nt element stride
#define BSTR_NN 72     // Bs_nn element stride
#define A_ST (BM*ASTR)     // 5120 elems per stage
#define B_ST 2560          // max(64*40, 32*72)
#define NSTG 3

__device__ __forceinline__ void mma16816(float c[4], const unsigned a[4], const unsigned b[2]){
    asm volatile("mma.sync.aligned.m16n8k16.row.col.f32.bf16.bf16.f32 "
                 "{%0,%1,%2,%3}, {%4,%5,%6,%7}, {%8,%9}, {%0,%1,%2,%3};"
                 : "+f"(c[0]), "+f"(c[1]), "+f"(c[2]), "+f"(c[3])
                 : "r"(a[0]), "r"(a[1]), "r"(a[2]), "r"(a[3]), "r"(b[0]), "r"(b[1]));
}
__device__ __forceinline__ void cp16(unsigned dst, const void* src, int bytes){
    asm volatile("cp.async.ca.shared.global [%0], [%1], 16, %2;" :: "r"(dst), "l"(src), "r"(bytes));
}
__device__ __forceinline__ void cp_commit(){ asm volatile("cp.async.commit_group;"); }
__device__ __forceinline__ void cp_wait1(){ asm volatile("cp.async.wait_group 1;"); }
__device__ __forceinline__ int clampb(int rem){ return rem < 0 ? 0 : (rem > 16 ? 16 : rem); }

template<bool TRANS_B, class Epi>
__global__ __launch_bounds__(256, 2) void gemm_bf(const bf16* __restrict__ A,
        const bf16* __restrict__ Bm, int M, int N, int K, int lda, int ldb,
        long sA, long sB, Epi epi)
{
    int bz = blockIdx.z;
    A  += (size_t)bz * sA;
    Bm += (size_t)bz * sB;
    __shared__ bf16 smA[NSTG][A_ST];
    __shared__ bf16 smB[NSTG][B_ST];
    int row0 = blockIdx.y*BM, col0 = blockIdx.x*BN;
    int tid = threadIdx.x, warp = tid>>5, lane = tid&31;
    int wm = warp>>1, wn = warp&1;
    int g = lane>>4;           // 0/1 for A-ldmatrix col group
    int gr8 = lane>>2, t4 = lane&3;

    unsigned aS = (unsigned)__cvta_generic_to_shared(&smA[0][0]);
    unsigned bS = (unsigned)__cvta_generic_to_shared(&smB[0][0]);

    // ---------- producer setup (incremental global pointers) ----------
    int ar = tid>>2;            // A row within tile (pass adds +64)
    int ak = (tid&3)*8;         // A k-col
    bool vA0 = (row0 + ar)      < M;
    bool vA1 = (row0 + ar + 64) < M;
    const bf16* pA0 = A + (size_t)(row0 + ar)      * lda + ak;
    const bf16* pA1 = A + (size_t)(row0 + ar + 64) * lda + ak;
    unsigned dA0 = aS + (unsigned)((ar*ASTR + ak)*2);
    unsigned dA1 = aS + (unsigned)(((ar+64)*ASTR + ak)*2);

    int br_nt = tid>>2, bk_nt = (tid&3)*8;    // TRANS: n-row, k-col
    int br_nn = tid>>3, bk_nn = (tid&7)*8;    // NN:    k-row, n-col
    bool vB;
    const bf16* pB;
    unsigned dB;
    int constNB = 0;
    if (TRANS_B){
        vB = (col0 + br_nt) < N;
        pB = Bm + (size_t)(col0 + br_nt) * ldb + bk_nt;
        dB = bS + (unsigned)((br_nt*ASTR + bk_nt)*2);
    } else {
        int gn = col0 + bk_nn;
        vB = true;
        constNB = clampb((N - gn)*2);
        pB = Bm + (size_t)br_nn * ldb + gn;
        dB = bS + (unsigned)((br_nn*BSTR_NN + bk_nn)*2);
    }

    auto load_stage = [&](unsigned soA, unsigned soB, int kk){
        int bytes0 = vA0 ? clampb((K - (kk + ak))*2) : 0;
        int bytes1 = vA1 ? clampb((K - (kk + ak))*2) : 0;
        cp16(dA0 + soA, bytes0 ? (const void*)pA0 : (const void*)A, bytes0);
        cp16(dA1 + soA, bytes1 ? (const void*)pA1 : (const void*)A, bytes1);
        pA0 += BK; pA1 += BK;
        if (TRANS_B){
            int bytesB = vB ? clampb((K - (kk + bk_nt))*2) : 0;
            cp16(dB + soB, bytesB ? (const void*)pB : (const void*)Bm, bytesB);
            pB += BK;
        } else {
            int bytesB = ((kk + br_nn) < K) ? constNB : 0;
            cp16(dB + soB, bytesB ? (const void*)pB : (const void*)Bm, bytesB);
            pB += (size_t)BK * ldb;
        }
    };

    // ---------- consumer smem base addresses (hoisted) ----------
    unsigned aAddrBase = aS + (unsigned)(((wm*32 + (lane&15))*ASTR + g*8)*2);
    unsigned bAddrBase;
    if (TRANS_B){
        int m = lane>>3, i = lane&7;
        int rowoff = i + ((m>>1)<<3);
        int kcoff  = (m&1)<<3;
        bAddrBase = bS + (unsigned)(((wn*32 + rowoff)*ASTR + kcoff)*2);
    } else {
        int m = lane>>3, i = lane&7;
        int krow = i + ((m&1)<<3);
        int ncoff = (m>>1)<<3;
        bAddrBase = bS + (unsigned)((krow*BSTR_NN + wn*32 + ncoff)*2);
    }

    float acc[2][4][4] = {};

    int nk = (K + BK - 1)/BK;
    load_stage(0, 0, 0);               cp_commit();
    load_stage(A_ST*2, B_ST*2, BK);    cp_commit();

    unsigned poA = 2*A_ST*2, poB = 2*B_ST*2;
    unsigned coA = 0,        coB = 0;

    for (int it = 0; it < nk; it++){
        cp_wait1();
        __syncthreads();
        if (it + 2 < nk) load_stage(poA, poB, (it+2)*BK);
        cp_commit();
        poA += A_ST*2; if (poA == NSTG*A_ST*2) poA = 0;
        poB += B_ST*2; if (poB == NSTG*B_ST*2) poB = 0;

        unsigned aAddr = aAddrBase + coA;
        unsigned bAddr = bAddrBase + coB;
        #pragma unroll
        for (int ks = 0; ks < 2; ks++){
            unsigned ra[2][4];
            #pragma unroll
            for (int mi = 0; mi < 2; mi++){
                unsigned ad = aAddr + (unsigned)((mi*16*ASTR + ks*16)*2);
                asm volatile("ldmatrix.sync.aligned.m8n8.x4.shared.b16 {%0,%1,%2,%3}, [%4];"
                    : "=r"(ra[mi][0]),"=r"(ra[mi][1]),"=r"(ra[mi][2]),"=r"(ra[mi][3]) : "r"(ad));
            }
            unsigned rb[4][2];
            #pragma unroll
            for (int h = 0; h < 2; h++){
                unsigned r0,r1,r2,r3;
                if (TRANS_B){
                    unsigned bd = bAddr + (unsigned)((h*16*ASTR + ks*16)*2);
                    asm volatile("ldmatrix.sync.aligned.m8n8.x4.shared.b16 {%0,%1,%2,%3}, [%4];"
                        : "=r"(r0),"=r"(r1),"=r"(r2),"=r"(r3) : "r"(bd));
                } else {
                    unsigned bd = bAddr + (unsigned)((ks*16*BSTR_NN + h*16)*2);
                    asm volatile("ldmatrix.sync.aligned.m8n8.x4.trans.shared.b16 {%0,%1,%2,%3}, [%4];"
                        : "=r"(r0),"=r"(r1),"=r"(r2),"=r"(r3) : "r"(bd));
                }
                rb[h*2][0]=r0; rb[h*2][1]=r1; rb[h*2+1][0]=r2; rb[h*2+1][1]=r3;
            }
            #pragma unroll
            for (int mi = 0; mi < 2; mi++)
                #pragma unroll
                for (int ni = 0; ni < 4; ni++)
                    mma16816(acc[mi][ni], ra[mi], rb[ni]);
        }
        coA += A_ST*2; if (coA == NSTG*A_ST*2) coA = 0;
        coB += B_ST*2; if (coB == NSTG*B_ST*2) coB = 0;
        __syncthreads();
    }

    #pragma unroll
    for (int mi = 0; mi < 2; mi++)
        #pragma unroll
        for (int ni = 0; ni < 4; ni++){
            int c = col0 + wn*32 + ni*8 + t4*2;
            int nv = (c + 1 < N) ? 2 : (c < N ? 1 : 0);
            if (nv){
                int r = row0 + wm*32 + mi*16 + gr8;
                if (r < M)     epi(bz, r,     c, acc[mi][ni][0], acc[mi][ni][1], nv);
                if (r + 8 < M) epi(bz, r + 8, c, acc[mi][ni][2], acc[mi][ni][3], nv);
            }
        }
}

// ---------------- epilogues (pair interface) ----------------
struct EpiH {
    const float* bh;
    __device__ void operator()(int, int r, int c, float a0, float a1, int nv) const {
        float s0 = silu_f(a0 + bh[c]);
        if (c < H_) g_v_bf[(size_t)r*H_ + c] = __float2bfloat16(s0);
        else        g_gate[(size_t)r*H_ + c - H_] = s0;
        if (nv == 2){
            float s1 = silu_f(a1 + bh[c+1]);
            if (c+1 < H_) g_v_bf[(size_t)r*H_ + c+1] = __float2bfloat16(s1);
            else          g_gate[(size_t)r*H_ + c+1 - H_] = s1;
        }
    }
};
struct EpiQK {   // fused silu + gamma/beta + rotary
    const float* bqk; const float* gamma; const float* beta;
    __device__ void operator()(int, int r, int c, float a0, float a1, int) const {
        int s = r % S_;
        float s0 = silu_f(a0 + bqk[c]);
        float s1 = silu_f(a1 + bqk[c+1]);
        float q0 = fmaf(s0, gamma[c],       beta[c]);
        float q1 = fmaf(s1, gamma[c+1],     beta[c+1]);
        float k0 = fmaf(s0, gamma[QK_+c],   beta[QK_+c]);
        float k1 = fmaf(s1, gamma[QK_+c+1], beta[QK_+c+1]);
        if (c < 32){
            float2 cs = g_rot[s*16 + (c>>1)];
            float q0n = q0*cs.x - q1*cs.y, q1n = q1*cs.x + q0*cs.y;
            float k0n = k0*cs.x - k1*cs.y, k1n = k1*cs.x + k0*cs.y;
            q0=q0n; q1=q1n; k0=k0n; k1=k1n;
        }
        size_t base = (size_t)r*QK_;
        g_q_bf[base+c]   = __float2bfloat16(q0);
        g_q_bf[base+c+1] = __float2bfloat16(q1);
        g_k_bf[base+c]   = __float2bfloat16(k0);
        g_k_bf[base+c+1] = __float2bfloat16(k1);
    }
};
struct EpiScores {
    const float* mask2;
    __device__ void operator()(int bz, int r, int c, float a0, float a1, int nv) const {
        size_t rowb = ((size_t)bz*S_ + r)*ATS;
        float v0 = a0 + g_bias[r - c + (S_-1)];
        float t0 = fmaxf(v0 * (1.0f/S_), 0.f);
        g_attn_bf[rowb + c] = __float2bfloat16(t0*t0*mask2[r*S_ + c]);
        if (nv == 2){
            float v1 = a1 + g_bias[r - c - 1 + (S_-1)];
            float t1 = fmaxf(v1 * (1.0f/S_), 0.f);
            g_attn_bf[rowb + c + 1] = __float2bfloat16(t1*t1*mask2[r*S_ + c + 1]);
        }
    }
};
struct EpiOut {
    __device__ __forceinline__ float gm(int bz, int r, int c) const {
        int rr = r % 5, cc = c % 5;
        if (rr == 4 || cc == 4) return 0.0f;
        int cnt = g_counts[bz*12000 + (r/5)*120 + (c/5)];
        return (cnt >= g_t2[bz]) ? 1.0f : 0.25f;
    }
    __device__ void operator()(int bz, int r, int c, float a0, float a1, int nv) const {
        size_t idx = ((size_t)bz*S_ + r)*H_ + c;
        g_o_bf[idx] = __float2bfloat16(gm(bz,r,c) * a0 * g_gate[idx]);
        if (nv == 2)
            g_o_bf[idx+1] = __float2bfloat16(gm(bz,r,c+1) * a1 * g_gate[idx+1]);
    }
};
struct EpiFinal {
    const float* bout; const float* x; float* out;
    __device__ void operator()(int, int r, int c, float a0, float a1, int nv) const {
        out[(size_t)r*D_ + c] = a0 + bout[c] + x[(size_t)r*D_ + c];
        if (nv == 2)
            out[(size_t)r*D_ + c + 1] = a1 + bout[c+1] + x[(size_t)r*D_ + c + 1];
    }
};

// ---------------- gate statistics ----------------
__global__ __launch_bounds__(256) void gate_hist_kernel(){
    int b = blockIdx.y;
    __shared__ int sh[129];
    __shared__ unsigned smax;
    int tid = threadIdx.x, lane = tid & 31;
    for (int i = tid; i < 129; i += 256) sh[i] = 0;
    if (tid == 0) smax = 0u;
    __syncthreads();
    const int n = S_*H_;
    unsigned localmax = 0u;
    int stride = gridDim.x * 256;
    for (int base = blockIdx.x*256; base < n; base += stride){
        int i = base + tid;
        bool valid = i < n;
        int bin = 130;
        if (valid){
            float gv = g_gate[(size_t)b*n + i];
            float a = fabsf(gv);
            bin = (int)floorf(a); if (bin > 128) bin = 128;
            unsigned u = __float_as_uint(gv);
            u = (u & 0x80000000u) ? ~u : (u | 0x80000000u);
            if (u > localmax) localmax = u;
        }
        unsigned m0 = __ballot_sync(0xffffffffu, bin == 0);
        if (valid && bin != 0) atomicAdd(&sh[bin], 1);
        if (lane == 0 && m0)   atomicAdd(&sh[0], __popc(m0));
    }
    atomicMax(&smax, localmax);
    __syncthreads();
    for (int i = tid; i < 129; i += 256) if (sh[i]) atomicAdd(&g_hist[b*129 + i], sh[i]);
    if (tid == 0) atomicMax(&g_gmax[b], smax);
}

__global__ void trim_kernel(){
    int b = threadIdx.x; if (b >= B_) return;
    unsigned u = g_gmax[b];
    u = (u & 0x80000000u) ? (u & 0x7FFFFFFFu) : ~u;
    float gmaxf = __uint_as_float(u);
    int gmax = (int)floorf(gmaxf);
    int cnt = 0, best = 0;
    for (int t = 128; t >= 1; t--){
        cnt += g_hist[b*129 + t];
        if (t <= gmax && cnt > 90000 && t > best) best = t;
    }
    g_trim[b] = best < 1 ? 1 : best;
}

__global__ __launch_bounds__(256) void counts_kernel(){
    int idx = blockIdx.x*256 + threadIdx.x;
    if (idx >= B_*100*120) return;
    int b = idx / 12000;
    int rem = idx % 12000;
    int i = rem / 120, j = rem % 120;
    float thr = (float)g_trim[b];
    const float* gb = g_gate + (size_t)b*S_*H_;
    int cnt = 0;
    #pragma unroll
    for (int r = 0; r < 4; r++)
        #pragma unroll
        for (int c = 0; c < 4; c++)
            cnt += (fabsf(gb[(i*5+r)*H_ + j*5+c]) >= thr);
    g_counts[idx] = (unsigned char)cnt;
    atomicMax(&g_cmax[b], cnt);
    atomicAdd(&g_hist2[b*17 + cnt], 1);
}

__global__ void t2_kernel(){
    int b = threadIdx.x; if (b >= B_) return;
    int cm = g_cmax[b];
    int cnt = 0, best = -1;
    for (int t = 16; t >= 1; t--){
        cnt += g_hist2[b*17 + t];
        if (t <= cm && cnt > 3600 && t > best) best = t;
    }
    g_t2[b] = (best >= 0) ? best : cm;
}

// ---------------- launch ----------------
extern "C" void kernel_launch(void* const* d_in, const int* in_sizes, int n_in,
                              void* d_out, int out_size){
    (void)in_sizes; (void)n_in; (void)out_size;
    const float* x       = (const float*)d_in[0];
    const float* mask2   = (const float*)d_in[1];
    const float* ln_g    = (const float*)d_in[2];
    const float* ln_b    = (const float*)d_in[3];
    const float* Wh      = (const float*)d_in[4];
    const float* bh      = (const float*)d_in[5];
    const float* Wqk     = (const float*)d_in[6];
    const float* bqk     = (const float*)d_in[7];
    const float* gamma   = (const float*)d_in[8];
    const float* beta    = (const float*)d_in[9];
    const float* rel_emb = (const float*)d_in[10];
    const float* Wout    = (const float*)d_in[11];
    const float* bout    = (const float*)d_in[12];
    float* out = (float*)d_out;

    bf16 *nx, *q, *k, *v, *attn, *o, *wh, *wqk, *wout;
    cudaGetSymbolAddress((void**)&nx,   g_nx_bf);
    cudaGetSymbolAddress((void**)&q,    g_q_bf);
    cudaGetSymbolAddress((void**)&k,    g_k_bf);
    cudaGetSymbolAddress((void**)&v,    g_v_bf);
    cudaGetSymbolAddress((void**)&attn, g_attn_bf);
    cudaGetSymbolAddress((void**)&o,    g_o_bf);
    cudaGetSymbolAddress((void**)&wh,   g_Wh_bf);
    cudaGetSymbolAddress((void**)&wqk,  g_Wqk_bf);
    cudaGetSymbolAddress((void**)&wout, g_Wout_bf);

    const int M = B_*S_;   // 10000

    setup_kernel<<<(D_*2*H_ + 255)/256, 256>>>(rel_emb, Wh, Wqk, Wout);
    ln_kernel<<<M/4, 128>>>(x, ln_g, ln_b);

    // h = silu(nx @ Wh + bh) -> v(bf16), gate(f32)
    gemm_bf<false><<<dim3((2*H_+BN-1)/BN, (M+BM-1)/BM, 1), 256>>>(
        nx, wh, M, 2*H_, D_, NXS, 2*H_, 0L, 0L, EpiH{bh});

    // qk -> fused silu + gamma/beta + rotary -> q,k (bf16)
    gemm_bf<false><<<dim3((QK_+BN-1)/BN, (M+BM-1)/BM, 1), 256>>>(
        nx, wqk, M, QK_, D_, NXS, QK_, 0L, 0L, EpiQK{bqk, gamma, beta});

    gate_hist_kernel<<<dim3(120, B_), 256>>>();
    trim_kernel<<<1, 32>>>();
    counts_kernel<<<(B_*100*120 + 255)/256, 256>>>();
    t2_kernel<<<1, 32>>>();

    // attn = (relu((q k^T + bias)/S))^2 * mask2   (batched NT)
    gemm_bf<true><<<dim3((S_+BN-1)/BN, (S_+BM-1)/BM, B_), 256>>>(
        q, k, S_, S_, QK_, QK_, QK_, (long)S_*QK_, (long)S_*QK_, EpiScores{mask2});

    // o = gm * (attn @ v) * gate  (batched NN)
    gemm_bf<false><<<dim3((H_+BN-1)/BN, (S_+BM-1)/BM, B_), 256>>>(
        attn, v, S_, H_, S_, ATS, H_, (long)S_*ATS, (long)S_*H_, EpiOut{});

    // out = o @ Wout + bout + x
    gemm_bf<false><<<dim3((D_+BN-1)/BN, (M+BM-1)/BM, 1), 256>>>(
        o, wout, M, D_, H_, H_, WOS, 0L, 0L, EpiFinal{bout, x, out});
}

// round 5
// speedup vs baseline: 6.2619x; 1.8727x over previous
#include <cuda_runtime.h>
#include <cuda_bf16.h>
#include <math.h>

#define B_  20
#define S_  500
#define D_  300
#define H_  600
#define QK_ 128
#define NXS 304      // nx row stride (16B aligned)
#define ATS 512      // attn row stride
#define WOS 304      // Wout row stride
#define NCAT 1328    // 2*H + QK, combined h/qk GEMM width (row stride too)

typedef __nv_bfloat16 bf16;

// ---------------- scratch (device globals; no allocation) ----------------
__device__ __align__(16) bf16  g_nx_bf[B_*S_*NXS];
__device__ __align__(16) bf16  g_q_bf[B_*S_*QK_];
__device__ __align__(16) bf16  g_k_bf[B_*S_*QK_];
__device__ __align__(16) bf16  g_v_bf[B_*S_*H_];
__device__ __align__(16) float g_gate[B_*S_*H_];
__device__ __align__(16) bf16  g_attn_bf[(size_t)B_*S_*ATS];
__device__ __align__(16) bf16  g_o_bf[B_*S_*H_];
__device__ __align__(16) bf16  g_Wcat[D_*NCAT];
__device__ float g_bcat[NCAT];
__device__ __align__(16) bf16  g_Wout_bf[H_*WOS];
__device__ float g_bias[1024];
__device__ float2 g_rot[S_*16];
__device__ int   g_hist[B_*129];
__device__ unsigned g_gmax[B_];
__device__ unsigned char g_counts[B_*100*120];
__device__ int   g_cmax[B_];
__device__ int   g_hist2[B_*17];

// ---------------- accurate fp32 exp (robust to fast-math) ----------------
__device__ __forceinline__ float my_expf(float x){
    x = fminf(fmaxf(x, -87.0f), 87.0f);
    float t = fmaf(x, 1.4426950408889634f, 12582912.0f);
    float n = t - 12582912.0f;
    float r = fmaf(n, -0.693359375f, x);
    r = fmaf(n, 2.1219444005469058e-4f, r);
    float p = 1.9841269841e-4f;
    p = fmaf(p, r, 1.3888888889e-3f);
    p = fmaf(p, r, 8.3333333333e-3f);
    p = fmaf(p, r, 4.1666666667e-2f);
    p = fmaf(p, r, 1.6666666667e-1f);
    p = fmaf(p, r, 0.5f);
    p = fmaf(p, r, 1.0f);
    p = fmaf(p, r, 1.0f);
    int e = (int)n;
    return p * __int_as_float((e + 127) << 23);
}
__device__ __forceinline__ float silu_f(float v){
    return v * __fdividef(1.0f, 1.0f + my_expf(-v));
}

// ------------- setup: zero stats, tables, weight conversion/concat -------------
__global__ void setup_kernel(const float* __restrict__ rel_emb,
                             const float* __restrict__ Wh,
                             const float* __restrict__ Wqk,
                             const float* __restrict__ Wout,
                             const float* __restrict__ bh,
                             const float* __restrict__ bqk){
    int i = blockIdx.x * blockDim.x + threadIdx.x;
    if (i < B_*129) g_hist[i] = 0;
    if (i < B_*17)  g_hist2[i] = 0;
    if (i < B_)     { g_gmax[i] = 0u; g_cmax[i] = 0; }
    if (i < 999){
        int n = i - (S_-1);
        int ret = (n < 0) ? 16 : 0;
        int na = n < 0 ? -n : n;
        int bucket;
        if (na < 8) bucket = ret + na;
        else {
            float lnum = (float)log((double)na / 8.0);
            float lden = (float)log(16.0);
            float q = (float)((double)lnum / (double)lden);
            int vil = 8 + (int)(q * 8.0f);
            if (vil > 15) vil = 15;
            bucket = ret + vil;
        }
        g_bias[i] = rel_emb[bucket] * sqrtf(128.0f);
    }
    if (i < S_*16){
        int s = i >> 4, f = i & 15;
        double inv = pow(10000.0, -(double)(2*f)/32.0);
        float fr = (float)s * (float)inv;
        g_rot[i] = make_float2((float)cos((double)fr), (float)sin((double)fr));
    }
    if (i < NCAT) g_bcat[i] = (i < 2*H_) ? bh[i] : bqk[i - 2*H_];
    if (i < D_*NCAT){
        int row = i / NCAT, col = i % NCAT;
        float w = (col < 2*H_) ? Wh[row*(2*H_) + col] : Wqk[row*QK_ + (col - 2*H_)];
        g_Wcat[i] = __float2bfloat16(w);
    }
    if (i < H_*D_){
        int row = i / D_, col = i % D_;
        g_Wout_bf[row*WOS + col] = __float2bfloat16(Wout[i]);
    }
}

// ---------------- LayerNorm, warp-per-row, single-pass ----------------
__global__ __launch_bounds__(128) void ln_kernel(const float* __restrict__ x,
                                                 const float* __restrict__ g,
                                                 const float* __restrict__ b){
    int w = threadIdx.x >> 5, lane = threadIdx.x & 31;
    int bs = blockIdx.x * 4 + w;
    int batch = bs / S_, s = bs % S_;
    const float* xr = x + (size_t)bs * D_;
    float xv[10];
    float sum = 0.f, ss = 0.f;
    #pragma unroll
    for (int j = 0; j < 10; j++){
        int i = j*32 + lane;
        float v = (i < D_) ? xr[i] : 0.f;
        xv[j] = v; sum += v; ss = fmaf(v, v, ss);
    }
    #pragma unroll
    for (int o = 16; o; o >>= 1){
        sum += __shfl_xor_sync(0xffffffffu, sum, o);
        ss  += __shfl_xor_sync(0xffffffffu, ss,  o);
    }
    float mean = sum * (1.0f / D_);
    float var  = ss * (1.0f / D_) - mean*mean;
    float inv  = rsqrtf(var + 1e-5f);
    size_t selfRow = (size_t)bs * NXS;
    size_t nextRow = ((size_t)batch*S_ + s + 1) * NXS;
    #pragma unroll
    for (int j = 0; j < 10; j++){
        int i = j*32 + lane;
        if (i >= D_) break;
        float val = (xv[j]-mean)*inv*g[i] + b[i];
        if (i < D_/2){
            if (s+1 < S_) g_nx_bf[nextRow + i] = __float2bfloat16(val);
        } else {
            g_nx_bf[selfRow + i] = __float2bfloat16(val);
        }
    }
    if (s == 0){
        #pragma unroll
        for (int j = 0; j < 5; j++){
            int i = j*32 + lane;
            if (i < D_/2) g_nx_bf[selfRow + i] = __float2bfloat16(0.f);
        }
    }
}

// ========== bf16 mma.sync GEMM: 3-stage cp.async, ONE sync/iter ==========
#define BM 128
#define BN 64
#define BK 32
#define ASTR 40
#define BSTR_NN 72
#define A_ST (BM*ASTR)
#define B_ST 2560
#define NSTG 3

__device__ __forceinline__ void mma16816(float c[4], const unsigned a[4], const unsigned b[2]){
    asm volatile("mma.sync.aligned.m16n8k16.row.col.f32.bf16.bf16.f32 "
                 "{%0,%1,%2,%3}, {%4,%5,%6,%7}, {%8,%9}, {%0,%1,%2,%3};"
                 : "+f"(c[0]), "+f"(c[1]), "+f"(c[2]), "+f"(c[3])
                 : "r"(a[0]), "r"(a[1]), "r"(a[2]), "r"(a[3]), "r"(b[0]), "r"(b[1]));
}
__device__ __forceinline__ void cp16(unsigned dst, const void* src, int bytes){
    asm volatile("cp.async.ca.shared.global [%0], [%1], 16, %2;" :: "r"(dst), "l"(src), "r"(bytes));
}
__device__ __forceinline__ void cp_commit(){ asm volatile("cp.async.commit_group;"); }
__device__ __forceinline__ void cp_wait1(){ asm volatile("cp.async.wait_group 1;"); }
__device__ __forceinline__ int clampb(int rem){ return rem < 0 ? 0 : (rem > 16 ? 16 : rem); }

template<bool TRANS_B, class Epi>
__global__ __launch_bounds__(256, 2) void gemm_bf(const bf16* __restrict__ A,
        const bf16* __restrict__ Bm, int M, int N, int K, int lda, int ldb,
        long sA, long sB, Epi epi)
{
    int bz = blockIdx.z;
    A  += (size_t)bz * sA;
    Bm += (size_t)bz * sB;
    __shared__ bf16 smA[NSTG][A_ST];
    __shared__ bf16 smB[NSTG][B_ST];
    int row0 = blockIdx.y*BM, col0 = blockIdx.x*BN;
    int tid = threadIdx.x, warp = tid>>5, lane = tid&31;
    int wm = warp>>1, wn = warp&1;
    int g = lane>>4;
    int gr8 = lane>>2, t4 = lane&3;

    unsigned aS = (unsigned)__cvta_generic_to_shared(&smA[0][0]);
    unsigned bS = (unsigned)__cvta_generic_to_shared(&smB[0][0]);

    int ar = tid>>2;
    int ak = (tid&3)*8;
    bool vA0 = (row0 + ar)      < M;
    bool vA1 = (row0 + ar + 64) < M;
    const bf16* pA0 = A + (size_t)(row0 + ar)      * lda + ak;
    const bf16* pA1 = A + (size_t)(row0 + ar + 64) * lda + ak;
    unsigned dA0 = aS + (unsigned)((ar*ASTR + ak)*2);
    unsigned dA1 = aS + (unsigned)(((ar+64)*ASTR + ak)*2);

    int br_nt = tid>>2, bk_nt = (tid&3)*8;
    int br_nn = tid>>3, bk_nn = (tid&7)*8;
    bool vB;
    const bf16* pB;
    unsigned dB;
    int constNB = 0;
    if (TRANS_B){
        vB = (col0 + br_nt) < N;
        pB = Bm + (size_t)(col0 + br_nt) * ldb + bk_nt;
        dB = bS + (unsigned)((br_nt*ASTR + bk_nt)*2);
    } else {
        int gn = col0 + bk_nn;
        vB = true;
        constNB = clampb((N - gn)*2);
        pB = Bm + (size_t)br_nn * ldb + gn;
        dB = bS + (unsigned)((br_nn*BSTR_NN + bk_nn)*2);
    }

    auto load_stage = [&](unsigned soA, unsigned soB, int kk){
        int bytes0 = vA0 ? clampb((K - (kk + ak))*2) : 0;
        int bytes1 = vA1 ? clampb((K - (kk + ak))*2) : 0;
        cp16(dA0 + soA, bytes0 ? (const void*)pA0 : (const void*)A, bytes0);
        cp16(dA1 + soA, bytes1 ? (const void*)pA1 : (const void*)A, bytes1);
        pA0 += BK; pA1 += BK;
        if (TRANS_B){
            int bytesB = vB ? clampb((K - (kk + bk_nt))*2) : 0;
            cp16(dB + soB, bytesB ? (const void*)pB : (const void*)Bm, bytesB);
            pB += BK;
        } else {
            int bytesB = ((kk + br_nn) < K) ? constNB : 0;
            cp16(dB + soB, bytesB ? (const void*)pB : (const void*)Bm, bytesB);
            pB += (size_t)BK * ldb;
        }
    };

    unsigned aAddrBase = aS + (unsigned)(((wm*32 + (lane&15))*ASTR + g*8)*2);
    unsigned bAddrBase;
    if (TRANS_B){
        int m = lane>>3, i = lane&7;
        int rowoff = i + ((m>>1)<<3);
        int kcoff  = (m&1)<<3;
        bAddrBase = bS + (unsigned)(((wn*32 + rowoff)*ASTR + kcoff)*2);
    } else {
        int m = lane>>3, i = lane&7;
        int krow = i + ((m&1)<<3);
        int ncoff = (m>>1)<<3;
        bAddrBase = bS + (unsigned)((krow*BSTR_NN + wn*32 + ncoff)*2);
    }

    float acc[2][4][4] = {};

    int nk = (K + BK - 1)/BK;
    load_stage(0, 0, 0);               cp_commit();
    load_stage(A_ST*2, B_ST*2, BK);    cp_commit();

    unsigned poA = 2*A_ST*2, poB = 2*B_ST*2;
    unsigned coA = 0,        coB = 0;

    for (int it = 0; it < nk; it++){
        cp_wait1();
        __syncthreads();
        if (it + 2 < nk) load_stage(poA, poB, (it+2)*BK);
        cp_commit();
        poA += A_ST*2; if (poA == NSTG*A_ST*2) poA = 0;
        poB += B_ST*2; if (poB == NSTG*B_ST*2) poB = 0;

        unsigned aAddr = aAddrBase + coA;
        unsigned bAddr = bAddrBase + coB;
        #pragma unroll
        for (int ks = 0; ks < 2; ks++){
            unsigned ra[2][4];
            #pragma unroll
            for (int mi = 0; mi < 2; mi++){
                unsigned ad = aAddr + (unsigned)((mi*16*ASTR + ks*16)*2);
                asm volatile("ldmatrix.sync.aligned.m8n8.x4.shared.b16 {%0,%1,%2,%3}, [%4];"
                    : "=r"(ra[mi][0]),"=r"(ra[mi][1]),"=r"(ra[mi][2]),"=r"(ra[mi][3]) : "r"(ad));
            }
            unsigned rb[4][2];
            #pragma unroll
            for (int h = 0; h < 2; h++){
                unsigned r0,r1,r2,r3;
                if (TRANS_B){
                    unsigned bd = bAddr + (unsigned)((h*16*ASTR + ks*16)*2);
                    asm volatile("ldmatrix.sync.aligned.m8n8.x4.shared.b16 {%0,%1,%2,%3}, [%4];"
                        : "=r"(r0),"=r"(r1),"=r"(r2),"=r"(r3) : "r"(bd));
                } else {
                    unsigned bd = bAddr + (unsigned)((ks*16*BSTR_NN + h*16)*2);
                    asm volatile("ldmatrix.sync.aligned.m8n8.x4.trans.shared.b16 {%0,%1,%2,%3}, [%4];"
                        : "=r"(r0),"=r"(r1),"=r"(r2),"=r"(r3) : "r"(bd));
                }
                rb[h*2][0]=r0; rb[h*2][1]=r1; rb[h*2+1][0]=r2; rb[h*2+1][1]=r3;
            }
            #pragma unroll
            for (int mi = 0; mi < 2; mi++)
                #pragma unroll
                for (int ni = 0; ni < 4; ni++)
                    mma16816(acc[mi][ni], ra[mi], rb[ni]);
        }
        coA += A_ST*2; if (coA == NSTG*A_ST*2) coA = 0;
        coB += B_ST*2; if (coB == NSTG*B_ST*2) coB = 0;
        // NOTE: no trailing sync — stage overwritten at iter it is (it-1)%3,
        // whose readers all passed the top barrier of iter it.
    }

    #pragma unroll
    for (int mi = 0; mi < 2; mi++)
        #pragma unroll
        for (int ni = 0; ni < 4; ni++){
            int c = col0 + wn*32 + ni*8 + t4*2;
            int nv = (c + 1 < N) ? 2 : (c < N ? 1 : 0);
            if (nv){
                int r = row0 + wm*32 + mi*16 + gr8;
                if (r < M)     epi(bz, r,     c, acc[mi][ni][0], acc[mi][ni][1], nv);
                if (r + 8 < M) epi(bz, r + 8, c, acc[mi][ni][2], acc[mi][ni][3], nv);
            }
        }
}

// ---------------- epilogues ----------------
struct EpiCat {   // combined h (c<1200) + qk (c>=1200) epilogue
    const float* gamma; const float* beta;
    __device__ void operator()(int, int r, int c, float a0, float a1, int nv) {
        if (c < 2*H_){
            float s0 = silu_f(a0 + g_bcat[c]);
            if (c < H_) g_v_bf[(size_t)r*H_ + c] = __float2bfloat16(s0);
            else        g_gate[(size_t)r*H_ + c - H_] = s0;
            if (nv == 2){
                float s1 = silu_f(a1 + g_bcat[c+1]);
                if (c+1 < H_) g_v_bf[(size_t)r*H_ + c+1] = __float2bfloat16(s1);
                else          g_gate[(size_t)r*H_ + c+1 - H_] = s1;
            }
        } else {
            int cq = c - 2*H_;
            int s = r % S_;
            float s0 = silu_f(a0 + g_bcat[c]);
            float s1 = silu_f(a1 + g_bcat[c+1]);
            float q0 = fmaf(s0, gamma[cq],        beta[cq]);
            float q1 = fmaf(s1, gamma[cq+1],      beta[cq+1]);
            float k0 = fmaf(s0, gamma[QK_+cq],    beta[QK_+cq]);
            float k1 = fmaf(s1, gamma[QK_+cq+1],  beta[QK_+cq+1]);
            if (cq < 32){
                float2 cs = g_rot[s*16 + (cq>>1)];
                float q0n = q0*cs.x - q1*cs.y, q1n = q1*cs.x + q0*cs.y;
                float k0n = k0*cs.x - k1*cs.y, k1n = k1*cs.x + k0*cs.y;
                q0=q0n; q1=q1n; k0=k0n; k1=k1n;
            }
            size_t base = (size_t)r*QK_;
            g_q_bf[base+cq]   = __float2bfloat16(q0);
            g_q_bf[base+cq+1] = __float2bfloat16(q1);
            g_k_bf[base+cq]   = __float2bfloat16(k0);
            g_k_bf[base+cq+1] = __float2bfloat16(k1);
        }
    }
};
struct EpiScores {
    const float* mask2;
    __device__ void operator()(int bz, int r, int c, float a0, float a1, int nv) {
        size_t rowb = ((size_t)bz*S_ + r)*ATS;
        float v0 = a0 + g_bias[r - c + (S_-1)];
        float t0 = fmaxf(v0 * (1.0f/S_), 0.f);
        g_attn_bf[rowb + c] = __float2bfloat16(t0*t0*mask2[r*S_ + c]);
        if (nv == 2){
            float v1 = a1 + g_bias[r - c - 1 + (S_-1)];
            float t1 = fmaxf(v1 * (1.0f/S_), 0.f);
            g_attn_bf[rowb + c + 1] = __float2bfloat16(t1*t1*mask2[r*S_ + c + 1]);
        }
    }
};
struct EpiOut {
    int t2c = -1;
    __device__ __forceinline__ int get_t2(int bz){
        if (t2c < 0){
            int cm = g_cmax[bz];
            int cnt = 0, best = -1;
            #pragma unroll
            for (int t = 16; t >= 1; t--){
                cnt += g_hist2[bz*17 + t];
                if (t <= cm && cnt > 3600 && t > best) best = t;
            }
            t2c = (best >= 0) ? best : cm;
        }
        return t2c;
    }
    __device__ __forceinline__ float gm(int bz, int r, int c, int t2){
        int rr = r % 5, cc = c % 5;
        if (rr == 4 || cc == 4) return 0.0f;
        int cnt = g_counts[bz*12000 + (r/5)*120 + (c/5)];
        return (cnt >= t2) ? 1.0f : 0.25f;
    }
    __device__ void operator()(int bz, int r, int c, float a0, float a1, int nv) {
        int t2 = get_t2(bz);
        size_t idx = ((size_t)bz*S_ + r)*H_ + c;
        g_o_bf[idx] = __float2bfloat16(gm(bz,r,c,t2) * a0 * g_gate[idx]);
        if (nv == 2)
            g_o_bf[idx+1] = __float2bfloat16(gm(bz,r,c+1,t2) * a1 * g_gate[idx+1]);
    }
};
struct EpiFinal {
    const float* bout; const float* x; float* out;
    __device__ void operator()(int, int r, int c, float a0, float a1, int nv) {
        out[(size_t)r*D_ + c] = a0 + bout[c] + x[(size_t)r*D_ + c];
        if (nv == 2)
            out[(size_t)r*D_ + c + 1] = a1 + bout[c+1] + x[(size_t)r*D_ + c + 1];
    }
};

// ---------------- gate statistics ----------------
__global__ __launch_bounds__(256) void gate_hist_kernel(){
    int b = blockIdx.y;
    __shared__ int sh[129];
    __shared__ unsigned smax;
    int tid = threadIdx.x, lane = tid & 31;
    for (int i = tid; i < 129; i += 256) sh[i] = 0;
    if (tid == 0) smax = 0u;
    __syncthreads();
    const float4* gp = reinterpret_cast<const float4*>(g_gate + (size_t)b*S_*H_);
    const int n4 = S_*H_/4;   // 75000
    int cnt0 = 0;
    unsigned localmax = 0u;
    int stride = gridDim.x * 256;
    for (int i = blockIdx.x*256 + tid; i < n4; i += stride){
        float4 v = gp[i];
        #pragma unroll
        for (int e = 0; e < 4; e++){
            float gv = (e==0)?v.x:(e==1)?v.y:(e==2)?v.z:v.w;
            float a = fabsf(gv);
            int bin = (int)floorf(a); if (bin > 128) bin = 128;
            if (bin == 0) cnt0++;
            else atomicAdd(&sh[bin], 1);
            unsigned u = __float_as_uint(gv);
            u = (u & 0x80000000u) ? ~u : (u | 0x80000000u);
            if (u > localmax) localmax = u;
        }
    }
    #pragma unroll
    for (int o = 16; o; o >>= 1){
        cnt0 += __shfl_xor_sync(0xffffffffu, cnt0, o);
        unsigned om = __shfl_xor_sync(0xffffffffu, localmax, o);
        if (om > localmax) localmax = om;
    }
    if (lane == 0){
        if (cnt0) atomicAdd(&sh[0], cnt0);
        atomicMax(&smax, localmax);
    }
    __syncthreads();
    for (int i = tid; i < 129; i += 256) if (sh[i]) atomicAdd(&g_hist[b*129 + i], sh[i]);
    if (tid == 0) atomicMax(&g_gmax[b], smax);
}

// counts with inline trim (per-CTA recompute from g_hist)
__global__ __launch_bounds__(256) void counts_kernel(){
    int b = blockIdx.y;
    __shared__ int shist[129];
    __shared__ int strim;
    __shared__ int sh2[17];
    __shared__ int scmax;
    int tid = threadIdx.x;
    if (tid < 129) shist[tid] = g_hist[b*129 + tid];
    if (tid < 17)  sh2[tid] = 0;
    if (tid == 0)  scmax = 0;
    __syncthreads();
    if (tid == 0){
        unsigned u = g_gmax[b];
        u = (u & 0x80000000u) ? (u & 0x7FFFFFFFu) : ~u;
        int gmax = (int)floorf(__uint_as_float(u));
        int cnt = 0, best = 0;
        for (int t = 128; t >= 1; t--){
            cnt += shist[t];
            if (t <= gmax && cnt > 90000 && t > best) best = t;
        }
        strim = best < 1 ? 1 : best;
    }
    __syncthreads();
    int idx = blockIdx.x*256 + tid;
    if (idx < 12000){
        int i = idx / 120, j = idx % 120;
        float thr = (float)strim;
        const float* gb = g_gate + (size_t)b*S_*H_;
        int cnt = 0;
        #pragma unroll
        for (int r = 0; r < 4; r++)
            #pragma unroll
            for (int c = 0; c < 4; c++)
                cnt += (fabsf(gb[(i*5+r)*H_ + j*5+c]) >= thr);
        g_counts[b*12000 + idx] = (unsigned char)cnt;
        atomicMax(&scmax, cnt);
        atomicAdd(&sh2[cnt], 1);
    }
    __syncthreads();
    if (tid < 17 && sh2[tid]) atomicAdd(&g_hist2[b*17 + tid], sh2[tid]);
    if (tid == 0) atomicMax(&g_cmax[b], scmax);
}

// ---------------- launch ----------------
extern "C" void kernel_launch(void* const* d_in, const int* in_sizes, int n_in,
                              void* d_out, int out_size){
    (void)in_sizes; (void)n_in; (void)out_size;
    const float* x       = (const float*)d_in[0];
    const float* mask2   = (const float*)d_in[1];
    const float* ln_g    = (const float*)d_in[2];
    const float* ln_b    = (const float*)d_in[3];
    const float* Wh      = (const float*)d_in[4];
    const float* bh      = (const float*)d_in[5];
    const float* Wqk     = (const float*)d_in[6];
    const float* bqk     = (const float*)d_in[7];
    const float* gamma   = (const float*)d_in[8];
    const float* beta    = (const float*)d_in[9];
    const float* rel_emb = (const float*)d_in[10];
    const float* Wout    = (const float*)d_in[11];
    const float* bout    = (const float*)d_in[12];
    float* out = (float*)d_out;

    bf16 *nx, *q, *k, *v, *attn, *o, *wcat, *wout;
    cudaGetSymbolAddress((void**)&nx,   g_nx_bf);
    cudaGetSymbolAddress((void**)&q,    g_q_bf);
    cudaGetSymbolAddress((void**)&k,    g_k_bf);
    cudaGetSymbolAddress((void**)&v,    g_v_bf);
    cudaGetSymbolAddress((void**)&attn, g_attn_bf);
    cudaGetSymbolAddress((void**)&o,    g_o_bf);
    cudaGetSymbolAddress((void**)&wcat, g_Wcat);
    cudaGetSymbolAddress((void**)&wout, g_Wout_bf);

    const int M = B_*S_;   // 10000

    setup_kernel<<<(D_*NCAT + 255)/256, 256>>>(rel_emb, Wh, Wqk, Wout, bh, bqk);
    ln_kernel<<<M/4, 128>>>(x, ln_g, ln_b);

    // combined: [h | qk] = silu(nx @ Wcat + bcat), with gamma/beta+rotary on qk region
    gemm_bf<false><<<dim3((NCAT+BN-1)/BN, (M+BM-1)/BM, 1), 256>>>(
        nx, wcat, M, NCAT, D_, NXS, NCAT, 0L, 0L, EpiCat{gamma, beta});

    // attn scores (needs q,k only)
    gemm_bf<true><<<dim3((S_+BN-1)/BN, (S_+BM-1)/BM, B_), 256>>>(
        q, k, S_, S_, QK_, QK_, QK_, (long)S_*QK_, (long)S_*QK_, EpiScores{mask2});

    gate_hist_kernel<<<dim3(38, B_), 256>>>();
    counts_kernel<<<dim3(47, B_), 256>>>();

    // o = gm * (attn @ v) * gate   (t2 computed lazily per-thread)
    gemm_bf<false><<<dim3((H_+BN-1)/BN, (S_+BM-1)/BM, B_), 256>>>(
        attn, v, S_, H_, S_, ATS, H_, (long)S_*ATS, (long)S_*H_, EpiOut{});

    // out = o @ Wout + bout + x
    gemm_bf<false><<<dim3((D_+BN-1)/BN, (M+BM-1)/BM, 1), 256>>>(
        o, wout, M, D_, H_, H_, WOS, 0L, 0L, EpiFinal{bout, x, out});
}

// round 6
// speedup vs baseline: 6.7850x; 1.0835x over previous
#include <cuda_runtime.h>
#include <cuda_bf16.h>
#include <math.h>

#define B_  20
#define S_  500
#define D_  300
#define H_  600
#define QK_ 128
#define NXS 304      // nx row stride (16B aligned)
#define ATS 512      // attn row stride
#define WOS 304      // Wout row stride
#define NCAT 1328    // 2*H + QK

typedef __nv_bfloat16 bf16;

// ---------------- scratch (device globals; no allocation) ----------------
__device__ __align__(16) bf16  g_nx_bf[B_*S_*NXS];
__device__ __align__(16) bf16  g_q_bf[B_*S_*QK_];
__device__ __align__(16) bf16  g_k_bf[B_*S_*QK_];
__device__ __align__(16) bf16  g_v_bf[B_*S_*H_];
__device__ __align__(16) float g_gate[B_*S_*H_];
__device__ __align__(16) bf16  g_attn_bf[(size_t)B_*S_*ATS];
__device__ __align__(16) bf16  g_o_bf[B_*S_*H_];
__device__ __align__(16) bf16  g_Wcat[D_*NCAT];
__device__ float g_bcat[NCAT];
__device__ __align__(16) bf16  g_Wout_bf[H_*WOS];
__device__ float g_bias[1024];
__device__ float2 g_rot[S_*16];
__device__ int   g_hist[B_*129];
__device__ unsigned g_gmax[B_];
__device__ unsigned char g_counts[B_*100*120];
__device__ int   g_cmax[B_];
__device__ int   g_hist2[B_*17];

// ---------------- accurate fp32 exp (robust to fast-math) ----------------
__device__ __forceinline__ float my_expf(float x){
    x = fminf(fmaxf(x, -87.0f), 87.0f);
    float t = fmaf(x, 1.4426950408889634f, 12582912.0f);
    float n = t - 12582912.0f;
    float r = fmaf(n, -0.693359375f, x);
    r = fmaf(n, 2.1219444005469058e-4f, r);
    float p = 1.9841269841e-4f;
    p = fmaf(p, r, 1.3888888889e-3f);
    p = fmaf(p, r, 8.3333333333e-3f);
    p = fmaf(p, r, 4.1666666667e-2f);
    p = fmaf(p, r, 1.6666666667e-1f);
    p = fmaf(p, r, 0.5f);
    p = fmaf(p, r, 1.0f);
    p = fmaf(p, r, 1.0f);
    int e = (int)n;
    return p * __int_as_float((e + 127) << 23);
}
__device__ __forceinline__ float silu_f(float v){
    return v * __fdividef(1.0f, 1.0f + my_expf(-v));
}
__device__ __forceinline__ void st_bf2(bf16* p, float lo, float hi){
    __nv_bfloat162 v;
    v.x = __float2bfloat16(lo);
    v.y = __float2bfloat16(hi);
    *reinterpret_cast<__nv_bfloat162*>(p) = v;
}

// ------------- setup -------------
__global__ void setup_kernel(const float* __restrict__ rel_emb,
                             const float* __restrict__ Wh,
                             const float* __restrict__ Wqk,
                             const float* __restrict__ Wout,
                             const float* __restrict__ bh,
                             const float* __restrict__ bqk){
    int i = blockIdx.x * blockDim.x + threadIdx.x;
    if (i < B_*129) g_hist[i] = 0;
    if (i < B_*17)  g_hist2[i] = 0;
    if (i < B_)     { g_gmax[i] = 0u; g_cmax[i] = 0; }
    if (i < 999){
        int n = i - (S_-1);
        int ret = (n < 0) ? 16 : 0;
        int na = n < 0 ? -n : n;
        int bucket;
        if (na < 8) bucket = ret + na;
        else {
            float lnum = (float)log((double)na / 8.0);
            float lden = (float)log(16.0);
            float q = (float)((double)lnum / (double)lden);
            int vil = 8 + (int)(q * 8.0f);
            if (vil > 15) vil = 15;
            bucket = ret + vil;
        }
        g_bias[i] = rel_emb[bucket] * sqrtf(128.0f);
    }
    if (i < S_*16){
        int s = i >> 4, f = i & 15;
        double inv = pow(10000.0, -(double)(2*f)/32.0);
        float fr = (float)s * (float)inv;
        g_rot[i] = make_float2((float)cos((double)fr), (float)sin((double)fr));
    }
    if (i < NCAT) g_bcat[i] = (i < 2*H_) ? bh[i] : bqk[i - 2*H_];
    if (i < D_*NCAT){
        int row = i / NCAT, col = i % NCAT;
        float w = (col < 2*H_) ? Wh[row*(2*H_) + col] : Wqk[row*QK_ + (col - 2*H_)];
        g_Wcat[i] = __float2bfloat16(w);
    }
    if (i < H_*D_){
        int row = i / D_, col = i % D_;
        g_Wout_bf[row*WOS + col] = __float2bfloat16(Wout[i]);
    }
}

// ---------------- LayerNorm, warp-per-row, single-pass ----------------
__global__ __launch_bounds__(128) void ln_kernel(const float* __restrict__ x,
                                                 const float* __restrict__ g,
                                                 const float* __restrict__ b){
    int w = threadIdx.x >> 5, lane = threadIdx.x & 31;
    int bs = blockIdx.x * 4 + w;
    int batch = bs / S_, s = bs % S_;
    const float* xr = x + (size_t)bs * D_;
    float xv[10];
    float sum = 0.f, ss = 0.f;
    #pragma unroll
    for (int j = 0; j < 10; j++){
        int i = j*32 + lane;
        float v = (i < D_) ? xr[i] : 0.f;
        xv[j] = v; sum += v; ss = fmaf(v, v, ss);
    }
    #pragma unroll
    for (int o = 16; o; o >>= 1){
        sum += __shfl_xor_sync(0xffffffffu, sum, o);
        ss  += __shfl_xor_sync(0xffffffffu, ss,  o);
    }
    float mean = sum * (1.0f / D_);
    float var  = ss * (1.0f / D_) - mean*mean;
    float inv  = rsqrtf(var + 1e-5f);
    size_t selfRow = (size_t)bs * NXS;
    size_t nextRow = ((size_t)batch*S_ + s + 1) * NXS;
    #pragma unroll
    for (int j = 0; j < 10; j++){
        int i = j*32 + lane;
        if (i >= D_) break;
        float val = (xv[j]-mean)*inv*g[i] + b[i];
        if (i < D_/2){
            if (s+1 < S_) g_nx_bf[nextRow + i] = __float2bfloat16(val);
        } else {
            g_nx_bf[selfRow + i] = __float2bfloat16(val);
        }
    }
    if (s == 0){
        #pragma unroll
        for (int j = 0; j < 5; j++){
            int i = j*32 + lane;
            if (i < D_/2) g_nx_bf[selfRow + i] = __float2bfloat16(0.f);
        }
    }
}

// ===== bf16 mma.sync GEMM: 128x128 CTA tile, 64x32 warp tile, 3-stage cp.async =====
#define BM 128
#define BN 128
#define BK 32
#define ASTR 40
#define BSTR_NN 136
#define A_ST (BM*ASTR)     // 5120
#define B_ST 5120          // max(128*40, 32*136=4352)
#define NSTG 3

__device__ __forceinline__ void mma16816(float c[4], const unsigned a[4], const unsigned b[2]){
    asm volatile("mma.sync.aligned.m16n8k16.row.col.f32.bf16.bf16.f32 "
                 "{%0,%1,%2,%3}, {%4,%5,%6,%7}, {%8,%9}, {%0,%1,%2,%3};"
                 : "+f"(c[0]), "+f"(c[1]), "+f"(c[2]), "+f"(c[3])
                 : "r"(a[0]), "r"(a[1]), "r"(a[2]), "r"(a[3]), "r"(b[0]), "r"(b[1]));
}
__device__ __forceinline__ void cp16(unsigned dst, const void* src, int bytes){
    asm volatile("cp.async.ca.shared.global [%0], [%1], 16, %2;" :: "r"(dst), "l"(src), "r"(bytes));
}
__device__ __forceinline__ void cp_commit(){ asm volatile("cp.async.commit_group;"); }
__device__ __forceinline__ void cp_wait1(){ asm volatile("cp.async.wait_group 1;"); }
__device__ __forceinline__ int clampb(int rem){ return rem < 0 ? 0 : (rem > 16 ? 16 : rem); }

template<bool TRANS_B, class Epi>
__global__ __launch_bounds__(256) void gemm_bf(const bf16* __restrict__ A,
        const bf16* __restrict__ Bm, int M, int N, int K, int lda, int ldb,
        long sA, long sB, Epi epi)
{
    int bz = blockIdx.z;
    A  += (size_t)bz * sA;
    Bm += (size_t)bz * sB;
    __shared__ bf16 smA[NSTG][A_ST];
    __shared__ bf16 smB[NSTG][B_ST];
    int row0 = blockIdx.y*BM, col0 = blockIdx.x*BN;
    int tid = threadIdx.x, warp = tid>>5, lane = tid&31;
    int wm = warp>>2, wn = warp&3;           // 2 x 4 warp grid
    int gr8 = lane>>2, t4 = lane&3;

    unsigned aS = (unsigned)__cvta_generic_to_shared(&smA[0][0]);
    unsigned bS = (unsigned)__cvta_generic_to_shared(&smB[0][0]);

    // ---- producer: A (128x32 per stage, 2 passes of 64 rows)
    int ar = tid>>2;
    int ak = (tid&3)*8;
    bool vA0 = (row0 + ar)      < M;
    bool vA1 = (row0 + ar + 64) < M;
    const bf16* pA0 = A + (size_t)(row0 + ar)      * lda + ak;
    const bf16* pA1 = A + (size_t)(row0 + ar + 64) * lda + ak;
    unsigned dA0 = aS + (unsigned)((ar*ASTR + ak)*2);
    unsigned dA1 = dA0 + (unsigned)(64*ASTR*2);

    // ---- producer: B
    bool vB0 = true, vB1 = true;
    const bf16* pB0; const bf16* pB1;
    unsigned dB0, dB1;
    int constNB = 0;
    int bk8 = 0, brow = 0;
    if (TRANS_B){
        brow = tid>>2; bk8 = (tid&3)*8;      // n-row, k-col; 2 passes of 64 rows
        vB0 = (col0 + brow)      < N;
        vB1 = (col0 + brow + 64) < N;
        pB0 = Bm + (size_t)(col0 + brow)      * ldb + bk8;
        pB1 = Bm + (size_t)(col0 + brow + 64) * ldb + bk8;
        dB0 = bS + (unsigned)((brow*ASTR + bk8)*2);
        dB1 = dB0 + (unsigned)(64*ASTR*2);
    } else {
        brow = tid>>4;                        // k-row 0..15; 2 passes of 16 rows
        int bc8 = (tid&15)*8;                 // n-col
        int gn = col0 + bc8;
        constNB = clampb((N - gn)*2);
        pB0 = Bm + (size_t)brow * ldb + gn;
        pB1 = pB0 + (size_t)16 * ldb;
        dB0 = bS + (unsigned)((brow*BSTR_NN + bc8)*2);
        dB1 = dB0 + (unsigned)(16*BSTR_NN*2);
    }

    auto load_stage = [&](unsigned soA, unsigned soB, int kk){
        int bytes0 = vA0 ? clampb((K - (kk + ak))*2) : 0;
        int bytes1 = vA1 ? clampb((K - (kk + ak))*2) : 0;
        cp16(dA0 + soA, bytes0 ? (const void*)pA0 : (const void*)A, bytes0);
        cp16(dA1 + soA, bytes1 ? (const void*)pA1 : (const void*)A, bytes1);
        pA0 += BK; pA1 += BK;
        if (TRANS_B){
            int kb = clampb((K - (kk + bk8))*2);
            int b0 = vB0 ? kb : 0;
            int b1 = vB1 ? kb : 0;
            cp16(dB0 + soB, b0 ? (const void*)pB0 : (const void*)Bm, b0);
            cp16(dB1 + soB, b1 ? (const void*)pB1 : (const void*)Bm, b1);
            pB0 += BK; pB1 += BK;
        } else {
            int b0 = ((kk + brow)      < K) ? constNB : 0;
            int b1 = ((kk + brow + 16) < K) ? constNB : 0;
            cp16(dB0 + soB, b0 ? (const void*)pB0 : (const void*)Bm, b0);
            cp16(dB1 + soB, b1 ? (const void*)pB1 : (const void*)Bm, b1);
            pB0 += (size_t)BK * ldb; pB1 += (size_t)BK * ldb;
        }
    };

    // ---- consumer smem base addresses
    unsigned aAddrBase = aS + (unsigned)(((wm*64 + (lane&15))*ASTR + (lane>>4)*8)*2);
    unsigned bAddrBase;
    {
        int m = lane>>3, i = lane&7;
        if (TRANS_B){
            int rowoff = i + ((m>>1)<<3);
            int kcoff  = (m&1)<<3;
            bAddrBase = bS + (unsigned)(((wn*32 + rowoff)*ASTR + kcoff)*2);
        } else {
            int krow = i + ((m&1)<<3);
            int ncoff = (m>>1)<<3;
            bAddrBase = bS + (unsigned)((krow*BSTR_NN + wn*32 + ncoff)*2);
        }
    }

    float acc[4][4][4] = {};

    int nk = (K + BK - 1)/BK;
    load_stage(0, 0, 0);               cp_commit();
    load_stage(A_ST*2, B_ST*2, BK);    cp_commit();

    unsigned poA = 2*A_ST*2, poB = 2*B_ST*2;
    unsigned coA = 0,        coB = 0;

    for (int it = 0; it < nk; it++){
        cp_wait1();
        __syncthreads();
        if (it + 2 < nk) load_stage(poA, poB, (it+2)*BK);
        cp_commit();
        poA += A_ST*2; if (poA == NSTG*A_ST*2) poA = 0;
        poB += B_ST*2; if (poB == NSTG*B_ST*2) poB = 0;

        unsigned aAddr = aAddrBase + coA;
        unsigned bAddr = bAddrBase + coB;
        #pragma unroll
        for (int ks = 0; ks < 2; ks++){
            unsigned ra[4][4];
            #pragma unroll
            for (int mi = 0; mi < 4; mi++){
                unsigned ad = aAddr + (unsigned)((mi*16*ASTR + ks*16)*2);
                asm volatile("ldmatrix.sync.aligned.m8n8.x4.shared.b16 {%0,%1,%2,%3}, [%4];"
                    : "=r"(ra[mi][0]),"=r"(ra[mi][1]),"=r"(ra[mi][2]),"=r"(ra[mi][3]) : "r"(ad));
            }
            unsigned rb[4][2];
            #pragma unroll
            for (int h = 0; h < 2; h++){
                unsigned r0,r1,r2,r3;
                if (TRANS_B){
                    unsigned bd = bAddr + (unsigned)((h*16*ASTR + ks*16)*2);
                    asm volatile("ldmatrix.sync.aligned.m8n8.x4.shared.b16 {%0,%1,%2,%3}, [%4];"
                        : "=r"(r0),"=r"(r1),"=r"(r2),"=r"(r3) : "r"(bd));
                } else {
                    unsigned bd = bAddr + (unsigned)((ks*16*BSTR_NN + h*16)*2);
                    asm volatile("ldmatrix.sync.aligned.m8n8.x4.trans.shared.b16 {%0,%1,%2,%3}, [%4];"
                        : "=r"(r0),"=r"(r1),"=r"(r2),"=r"(r3) : "r"(bd));
                }
                rb[h*2][0]=r0; rb[h*2][1]=r1; rb[h*2+1][0]=r2; rb[h*2+1][1]=r3;
            }
            #pragma unroll
            for (int mi = 0; mi < 4; mi++)
                #pragma unroll
                for (int ni = 0; ni < 4; ni++)
                    mma16816(acc[mi][ni], ra[mi], rb[ni]);
        }
        coA += A_ST*2; if (coA == NSTG*A_ST*2) coA = 0;
        coB += B_ST*2; if (coB == NSTG*B_ST*2) coB = 0;
        // no trailing sync: stage overwritten at iter it is (it-1)%3, readers passed top barrier
    }

    #pragma unroll
    for (int mi = 0; mi < 4; mi++)
        #pragma unroll
        for (int ni = 0; ni < 4; ni++){
            int c = col0 + wn*32 + ni*8 + t4*2;
            int nv = (c + 1 < N) ? 2 : (c < N ? 1 : 0);
            if (nv){
                int r = row0 + wm*64 + mi*16 + gr8;
                if (r < M)     epi(bz, r,     c, acc[mi][ni][0], acc[mi][ni][1], nv);
                if (r + 8 < M) epi(bz, r + 8, c, acc[mi][ni][2], acc[mi][ni][3], nv);
            }
        }
}

// ---------------- epilogues (c is always even; pair stores vectorized) ----------------
struct EpiCat {
    const float* gamma; const float* beta;
    __device__ void operator()(int, int r, int c, float a0, float a1, int nv) {
        if (c < 2*H_){
            float s0 = silu_f(a0 + g_bcat[c]);
            float s1 = silu_f(a1 + g_bcat[c+1]);
            if (c < H_)  st_bf2(&g_v_bf[(size_t)r*H_ + c], s0, s1);
            else *reinterpret_cast<float2*>(&g_gate[(size_t)r*H_ + c - H_]) = make_float2(s0, s1);
        } else {
            int cq = c - 2*H_;
            int s = r % S_;
            float s0 = silu_f(a0 + g_bcat[c]);
            float s1 = silu_f(a1 + g_bcat[c+1]);
            float q0 = fmaf(s0, gamma[cq],        beta[cq]);
            float q1 = fmaf(s1, gamma[cq+1],      beta[cq+1]);
            float k0 = fmaf(s0, gamma[QK_+cq],    beta[QK_+cq]);
            float k1 = fmaf(s1, gamma[QK_+cq+1],  beta[QK_+cq+1]);
            if (cq < 32){
                float2 cs = g_rot[s*16 + (cq>>1)];
                float q0n = q0*cs.x - q1*cs.y, q1n = q1*cs.x + q0*cs.y;
                float k0n = k0*cs.x - k1*cs.y, k1n = k1*cs.x + k0*cs.y;
                q0=q0n; q1=q1n; k0=k0n; k1=k1n;
            }
            size_t base = (size_t)r*QK_;
            st_bf2(&g_q_bf[base+cq], q0, q1);
            st_bf2(&g_k_bf[base+cq], k0, k1);
        }
    }
};
struct EpiScores {
    const float* mask2;
    __device__ void operator()(int bz, int r, int c, float a0, float a1, int nv) {
        size_t rowb = ((size_t)bz*S_ + r)*ATS;
        if (nv == 2){
            float2 mk = *reinterpret_cast<const float2*>(&mask2[r*S_ + c]);
            float v0 = a0 + g_bias[r - c + (S_-1)];
            float v1 = a1 + g_bias[r - c - 1 + (S_-1)];
            float t0 = fmaxf(v0 * (1.0f/S_), 0.f);
            float t1 = fmaxf(v1 * (1.0f/S_), 0.f);
            st_bf2(&g_attn_bf[rowb + c], t0*t0*mk.x, t1*t1*mk.y);
        } else {
            float v0 = a0 + g_bias[r - c + (S_-1)];
            float t0 = fmaxf(v0 * (1.0f/S_), 0.f);
            g_attn_bf[rowb + c] = __float2bfloat16(t0*t0*mask2[r*S_ + c]);
        }
    }
};
struct EpiOut {
    int t2c = -1;
    __device__ __forceinline__ int get_t2(int bz){
        if (t2c < 0){
            int cm = g_cmax[bz];
            int cnt = 0, best = -1;
            #pragma unroll
            for (int t = 16; t >= 1; t--){
                cnt += g_hist2[bz*17 + t];
                if (t <= cm && cnt > 3600 && t > best) best = t;
            }
            t2c = (best >= 0) ? best : cm;
        }
        return t2c;
    }
    __device__ __forceinline__ float gm(int bz, int r, int c, int t2){
        int rr = r % 5, cc = c % 5;
        if (rr == 4 || cc == 4) return 0.0f;
        int cnt = g_counts[bz*12000 + (r/5)*120 + (c/5)];
        return (cnt >= t2) ? 1.0f : 0.25f;
    }
    __device__ void operator()(int bz, int r, int c, float a0, float a1, int nv) {
        int t2 = get_t2(bz);
        size_t idx = ((size_t)bz*S_ + r)*H_ + c;
        if (nv == 2){
            float2 gt = *reinterpret_cast<const float2*>(&g_gate[idx]);
            st_bf2(&g_o_bf[idx], gm(bz,r,c,t2) * a0 * gt.x, gm(bz,r,c+1,t2) * a1 * gt.y);
        } else {
            g_o_bf[idx] = __float2bfloat16(gm(bz,r,c,t2) * a0 * g_gate[idx]);
        }
    }
};
struct EpiFinal {
    const float* bout; const float* x; float* out;
    __device__ void operator()(int, int r, int c, float a0, float a1, int nv) {
        size_t idx = (size_t)r*D_ + c;
        if (nv == 2){
            float2 xv = *reinterpret_cast<const float2*>(&x[idx]);
            *reinterpret_cast<float2*>(&out[idx]) =
                make_float2(a0 + bout[c] + xv.x, a1 + bout[c+1] + xv.y);
        } else {
            out[idx] = a0 + bout[c] + x[idx];
        }
    }
};

// ---------------- gate statistics ----------------
__global__ __launch_bounds__(256) void gate_hist_kernel(){
    int b = blockIdx.y;
    __shared__ int sh[129];
    __shared__ unsigned smax;
    int tid = threadIdx.x, lane = tid & 31;
    for (int i = tid; i < 129; i += 256) sh[i] = 0;
    if (tid == 0) smax = 0u;
    __syncthreads();
    const float4* gp = reinterpret_cast<const float4*>(g_gate + (size_t)b*S_*H_);
    const int n4 = S_*H_/4;
    int cnt0 = 0;
    unsigned localmax = 0u;
    int stride = gridDim.x * 256;
    for (int i = blockIdx.x*256 + tid; i < n4; i += stride){
        float4 v = gp[i];
        #pragma unroll
        for (int e = 0; e < 4; e++){
            float gv = (e==0)?v.x:(e==1)?v.y:(e==2)?v.z:v.w;
            float a = fabsf(gv);
            int bin = (int)floorf(a); if (bin > 128) bin = 128;
            if (bin == 0) cnt0++;
            else atomicAdd(&sh[bin], 1);
            unsigned u = __float_as_uint(gv);
            u = (u & 0x80000000u) ? ~u : (u | 0x80000000u);
            if (u > localmax) localmax = u;
        }
    }
    #pragma unroll
    for (int o = 16; o; o >>= 1){
        cnt0 += __shfl_xor_sync(0xffffffffu, cnt0, o);
        unsigned om = __shfl_xor_sync(0xffffffffu, localmax, o);
        if (om > localmax) localmax = om;
    }
    if (lane == 0){
        if (cnt0) atomicAdd(&sh[0], cnt0);
        atomicMax(&smax, localmax);
    }
    __syncthreads();
    for (int i = tid; i < 129; i += 256) if (sh[i]) atomicAdd(&g_hist[b*129 + i], sh[i]);
    if (tid == 0) atomicMax(&g_gmax[b], smax);
}

__global__ __launch_bounds__(256) void counts_kernel(){
    int b = blockIdx.y;
    __shared__ int shist[129];
    __shared__ int strim;
    __shared__ int sh2[17];
    __shared__ int scmax;
    int tid = threadIdx.x;
    if (tid < 129) shist[tid] = g_hist[b*129 + tid];
    if (tid < 17)  sh2[tid] = 0;
    if (tid == 0)  scmax = 0;
    __syncthreads();
    if (tid == 0){
        unsigned u = g_gmax[b];
        u = (u & 0x80000000u) ? (u & 0x7FFFFFFFu) : ~u;
        int gmax = (int)floorf(__uint_as_float(u));
        int cnt = 0, best = 0;
        for (int t = 128; t >= 1; t--){
            cnt += shist[t];
            if (t <= gmax && cnt > 90000 && t > best) best = t;
        }
        strim = best < 1 ? 1 : best;
    }
    __syncthreads();
    int idx = blockIdx.x*256 + tid;
    if (idx < 12000){
        int i = idx / 120, j = idx % 120;
        float thr = (float)strim;
        const float* gb = g_gate + (size_t)b*S_*H_;
        int cnt = 0;
        #pragma unroll
        for (int r = 0; r < 4; r++)
            #pragma unroll
            for (int c = 0; c < 4; c++)
                cnt += (fabsf(gb[(i*5+r)*H_ + j*5+c]) >= thr);
        g_counts[b*12000 + idx] = (unsigned char)cnt;
        atomicMax(&scmax, cnt);
        atomicAdd(&sh2[cnt], 1);
    }
    __syncthreads();
    if (tid < 17 && sh2[tid]) atomicAdd(&g_hist2[b*17 + tid], sh2[tid]);
    if (tid == 0) atomicMax(&g_cmax[b], scmax);
}

// ---------------- launch ----------------
extern "C" void kernel_launch(void* const* d_in, const int* in_sizes, int n_in,
                              void* d_out, int out_size){
    (void)in_sizes; (void)n_in; (void)out_size;
    const float* x       = (const float*)d_in[0];
    const float* mask2   = (const float*)d_in[1];
    const float* ln_g    = (const float*)d_in[2];
    const float* ln_b    = (const float*)d_in[3];
    const float* Wh      = (const float*)d_in[4];
    const float* bh      = (const float*)d_in[5];
    const float* Wqk     = (const float*)d_in[6];
    const float* bqk     = (const float*)d_in[7];
    const float* gamma   = (const float*)d_in[8];
    const float* beta    = (const float*)d_in[9];
    const float* rel_emb = (const float*)d_in[10];
    const float* Wout    = (const float*)d_in[11];
    const float* bout    = (const float*)d_in[12];
    float* out = (float*)d_out;

    bf16 *nx, *q, *k, *v, *attn, *o, *wcat, *wout;
    cudaGetSymbolAddress((void**)&nx,   g_nx_bf);
    cudaGetSymbolAddress((void**)&q,    g_q_bf);
    cudaGetSymbolAddress((void**)&k,    g_k_bf);
    cudaGetSymbolAddress((void**)&v,    g_v_bf);
    cudaGetSymbolAddress((void**)&attn, g_attn_bf);
    cudaGetSymbolAddress((void**)&o,    g_o_bf);
    cudaGetSymbolAddress((void**)&wcat, g_Wcat);
    cudaGetSymbolAddress((void**)&wout, g_Wout_bf);

    const int M = B_*S_;   // 10000

    setup_kernel<<<(D_*NCAT + 255)/256, 256>>>(rel_emb, Wh, Wqk, Wout, bh, bqk);
    ln_kernel<<<M/4, 128>>>(x, ln_g, ln_b);

    // combined: [h | qk] = silu(nx @ Wcat + bcat), gamma/beta+rotary fused on qk region
    gemm_bf<false><<<dim3((NCAT+BN-1)/BN, (M+BM-1)/BM, 1), 256>>>(
        nx, wcat, M, NCAT, D_, NXS, NCAT, 0L, 0L, EpiCat{gamma, beta});

    // attn scores (batched NT)
    gemm_bf<true><<<dim3((S_+BN-1)/BN, (S_+BM-1)/BM, B_), 256>>>(
        q, k, S_, S_, QK_, QK_, QK_, (long)S_*QK_, (long)S_*QK_, EpiScores{mask2});

    gate_hist_kernel<<<dim3(38, B_), 256>>>();
    counts_kernel<<<dim3(47, B_), 256>>>();

    // o = gm * (attn @ v) * gate
    gemm_bf<false><<<dim3((H_+BN-1)/BN, (S_+BM-1)/BM, B_), 256>>>(
        attn, v, S_, H_, S_, ATS, H_, (long)S_*ATS, (long)S_*H_, EpiOut{});

    // out = o @ Wout + bout + x
    gemm_bf<false><<<dim3((D_+BN-1)/BN, (M+BM-1)/BM, 1), 256>>>(
        o, wout, M, D_, H_, H_, WOS, 0L, 0L, EpiFinal{bout, x, out});
}